// round 15
// baseline (speedup 1.0000x reference)
#include <cuda_runtime.h>
#include <cuda_fp16.h>
#include <math.h>
#include <stdint.h>

#define Nn 256
#define Ll 384
#define Hh 8
#define Dd 32
#define HD 256
#define NL (Nn*Ll)
#define LLc (Ll*Ll)
#define HLL (Hh*LLc)
#define ISD 0.17677669529663687f

// fp32 scratch
__device__ float g_qsw[Ll*HD];
__device__ float g_ksw[NL*HD];
__device__ float g_mq[NL*HD];
__device__ float g_gate[NL*HD];
__device__ float g_sw[NL*Hh];
__device__ float g_pb[HLL];
__device__ float g_attn[2*HLL];       // two split-K partials
// fp16 operands
__device__ __half g_at[NL*HD];
__device__ __half g_wt[6*256*256];
__device__ __half g_kt[NL*HD];
__device__ __half g_qst[NL*HD];
__device__ __half g_pt[HLL];
__device__ __half g_vT[NL*HD];
__device__ __half g_og[NL*HD];

// ---------------- helpers ----------------------------------------------------
__device__ __forceinline__ unsigned f2tf(float x){
  unsigned u; asm("cvt.rna.tf32.f32 %0, %1;" : "=r"(u) : "f"(x)); return u;
}
__device__ __forceinline__ unsigned pk2(float x, float y){
  __half2 h = __floats2half2_rn(x, y);
  return *(unsigned*)&h;
}
__device__ __forceinline__ void mma_f16(float c[4], const unsigned a[4], const unsigned b[2]){
  asm volatile("mma.sync.aligned.m16n8k16.row.col.f32.f16.f16.f32 "
    "{%0,%1,%2,%3},{%4,%5,%6,%7},{%8,%9},{%0,%1,%2,%3};"
    : "+f"(c[0]),"+f"(c[1]),"+f"(c[2]),"+f"(c[3])
    : "r"(a[0]),"r"(a[1]),"r"(a[2]),"r"(a[3]),"r"(b[0]),"r"(b[1]));
}
__device__ __forceinline__ void mma_tf32(float c[4], const unsigned a[4], const unsigned b[2]){
  asm volatile("mma.sync.aligned.m16n8k8.row.col.f32.tf32.tf32.f32 "
    "{%0,%1,%2,%3},{%4,%5,%6,%7},{%8,%9},{%0,%1,%2,%3};"
    : "+f"(c[0]),"+f"(c[1]),"+f"(c[2]),"+f"(c[3])
    : "r"(a[0]),"r"(a[1]),"r"(a[2]),"r"(a[3]),"r"(b[0]),"r"(b[1]));
}
__device__ __forceinline__ void ldsm4(unsigned r[4], uint32_t a){
  asm volatile("ldmatrix.sync.aligned.m8n8.x4.shared.b16 {%0,%1,%2,%3}, [%4];"
    : "=r"(r[0]),"=r"(r[1]),"=r"(r[2]),"=r"(r[3]) : "r"(a));
}
__device__ __forceinline__ uint32_t s2u(const void* p){
  uint32_t a; asm("{ .reg .u64 t; cvta.to.shared.u64 t, %1; cvt.u32.u64 %0, t; }" : "=r"(a) : "l"(p)); return a;
}
__device__ __forceinline__ void cpa16(uint32_t s, const void* g){
  asm volatile("cp.async.cg.shared.global [%0], [%1], 16;" :: "r"(s), "l"(g));
}
#define CPC() asm volatile("cp.async.commit_group;" ::: "memory")
#define CPW1() asm volatile("cp.async.wait_group 1;" ::: "memory")
#define CPW0() asm volatile("cp.async.wait_group 0;" ::: "memory")

__device__ __forceinline__ float warpSum(float v){
#pragma unroll
  for(int o=16;o;o>>=1) v += __shfl_xor_sync(0xffffffffu, v, o);
  return v;
}
__device__ __forceinline__ float warpMax(float v){
#pragma unroll
  for(int o=16;o;o>>=1) v = fmaxf(v, __shfl_xor_sync(0xffffffffu, v, o));
  return v;
}
__device__ __forceinline__ float blockSum(float v, float* red, int nw){
  int t=threadIdx.x; v=warpSum(v);
  if((t&31)==0) red[t>>5]=v;
  __syncthreads();
  float s=0.f;
  if(t<32){ s=(t<nw)?red[t]:0.f; s=warpSum(s); if(t==0) red[0]=s; }
  __syncthreads(); s=red[0]; __syncthreads(); return s;
}
__device__ __forceinline__ float blockMax(float v, float* red, int nw){
  int t=threadIdx.x; v=warpMax(v);
  if((t&31)==0) red[t>>5]=v;
  __syncthreads();
  float s=-3.4e38f;
  if(t<32){ s=(t<nw)?red[t]:-3.4e38f; s=warpMax(s); if(t==0) red[0]=s; }
  __syncthreads(); s=red[0]; __syncthreads(); return s;
}

// ---- prep: convert+transpose 6 weight mats to fp16 [mat][n][k] ---------------
__global__ void k_prep(const float* __restrict__ w0, const float* __restrict__ w1,
                       const float* __restrict__ w2, const float* __restrict__ w3,
                       const float* __restrict__ w4, const float* __restrict__ w5){
  int bid = blockIdx.x, t = threadIdx.x;
  int mat = bid>>8, n = bid&255;
  const float* W = (mat==0)?w0:(mat==1)?w1:(mat==2)?w2:(mat==3)?w3:(mat==4)?w4:w5;
  g_wt[(size_t)bid*256 + t] = __float2half_rn(W[t*256 + n]);
}

// ---- K_ln: LN(msa) -> fp16 g_at ----------------------------------------------
__global__ __launch_bounds__(256) void k_ln(const float* __restrict__ msa,
    const float* __restrict__ lng, const float* __restrict__ lnb){
  size_t r = (size_t)blockIdx.x*32 + (threadIdx.x>>3);
  int q = threadIdx.x&7;
  const float* rp = msa + r*HD + q*32;
  float4 xv[8];
  float s=0.f, ss=0.f;
#pragma unroll
  for(int f=0;f<8;f++){
    xv[f] = *(const float4*)(rp + f*4);
    s  += xv[f].x+xv[f].y+xv[f].z+xv[f].w;
    ss += xv[f].x*xv[f].x+xv[f].y*xv[f].y+xv[f].z*xv[f].z+xv[f].w*xv[f].w;
  }
#pragma unroll
  for(int o=1;o<8;o<<=1){ s += __shfl_xor_sync(0xffffffffu,s,o); ss += __shfl_xor_sync(0xffffffffu,ss,o); }
  float mean = s*(1.f/HD), inv = rsqrtf(ss*(1.f/HD)-mean*mean+1e-5f);
#pragma unroll
  for(int f=0;f<8;f++){
    int c = q*32 + f*4;
    uint2 o;
    o.x = pk2((xv[f].x-mean)*inv*lng[c  ]+lnb[c  ], (xv[f].y-mean)*inv*lng[c+1]+lnb[c+1]);
    o.y = pk2((xv[f].z-mean)*inv*lng[c+2]+lnb[c+2], (xv[f].w-mean)*inv*lng[c+3]+lnb[c+3]);
    *(uint2*)(g_at + r*HD + c) = o;
  }
}

// ---- K0: qsw row 0 -----------------------------------------------------------
__global__ void k_qsw(const float* __restrict__ msa, const float* __restrict__ lng,
                      const float* __restrict__ lnb, const float* __restrict__ swq,
                      const float* __restrict__ sbq){
  int i = blockIdx.x, t = threadIdx.x;
  __shared__ float sm[HD]; __shared__ float red[32];
  float x = msa[(size_t)i*HD + t];
  float mean = blockSum(x, red, 8)*(1.f/HD);
  float d = x-mean;
  float var = blockSum(d*d, red, 8)*(1.f/HD);
  sm[t] = d*rsqrtf(var+1e-5f)*lng[t]+lnb[t];
  __syncthreads();
  float acc = sbq[t];
#pragma unroll 8
  for(int r=0;r<HD;r++) acc += sm[r]*swq[r*HD+t];
  g_qsw[i*HD+t] = acc*ISD;
}

// ---- K1: 5 projections fp16, CTA 128x128, warp 32x64, K-chunk 64 -------------
#define PROJ_SMEM (2*36864)
__global__ __launch_bounds__(256) void k_proj(const float* __restrict__ sbk,
                                              const float* __restrict__ bg){
  extern __shared__ char dsm[];
  const uint32_t sb = s2u(dsm);
  const int t = threadIdx.x;
  const size_t row0 = (size_t)blockIdx.y*128;
  const int by = blockIdx.x;                 // 0..9
  const int mi = by>>1, nb = (by&1)*128;
  const int nn = (int)(row0/Ll);
  const int ibase = (int)(row0%Ll);
  const __half* Bsrc = g_wt + ((size_t)mi*256 + nb)*256;

  const int w = t>>5, lane = t&31;
  const int wm = w>>1, wn = w&1;
  const int qr = lane>>2, ql = lane&3;
  const uint32_t aLn = ((wm*32 + (lane&15))*72 + ((lane>>4)<<3))*2;
  const uint32_t bLn = ((wn*64 + (lane&7) + ((lane&16)>>1))*72 + (((lane>>3)&1)<<3))*2;

#pragma unroll
  for(int c=0;c<4;c++){ int u=c*256+t, r=u>>3, cu=u&7;
    cpa16(sb + r*144 + cu*16, g_at + (row0+r)*HD + cu*8); }
#pragma unroll
  for(int c=0;c<4;c++){ int u=c*256+t, r=u>>3, cu=u&7;
    cpa16(sb + 18432 + r*144 + cu*16, Bsrc + (size_t)r*256 + cu*8); }
  CPC();

  float acc[2][8][4];
#pragma unroll
  for(int am=0;am<2;am++)
#pragma unroll
    for(int bn=0;bn<8;bn++)
#pragma unroll
      for(int e=0;e<4;e++) acc[am][bn][e]=0.f;

  for(int kc=0;kc<4;kc++){
    if(kc+1<4){
      int k1 = (kc+1)*64;
      uint32_t dst = sb + ((kc+1)&1)*36864;
#pragma unroll
      for(int c=0;c<4;c++){ int u=c*256+t, r=u>>3, cu=u&7;
        cpa16(dst + r*144 + cu*16, g_at + (row0+r)*HD + k1 + cu*8); }
#pragma unroll
      for(int c=0;c<4;c++){ int u=c*256+t, r=u>>3, cu=u&7;
        cpa16(dst + 18432 + r*144 + cu*16, Bsrc + (size_t)r*256 + k1 + cu*8); }
      CPC(); CPW1();
    } else CPW0();
    __syncthreads();
    const uint32_t st = sb + (kc&1)*36864;
    const uint32_t bst = st + 18432;
#pragma unroll
    for(int ks=0;ks<4;ks++){
      const uint32_t kb = ks*32;
      unsigned a0[4], a1[4], bf[4][4];
      ldsm4(a0, st + aLn + kb);
      ldsm4(a1, st + aLn + 16*144 + kb);
#pragma unroll
      for(int q=0;q<4;q++) ldsm4(bf[q], bst + bLn + q*16*144 + kb);
#pragma unroll
      for(int bn=0;bn<8;bn++){
        mma_f16(acc[0][bn], a0, bf[bn>>1] + 2*(bn&1));
        mma_f16(acc[1][bn], a1, bf[bn>>1] + 2*(bn&1));
      }
    }
    __syncthreads();
  }
#pragma unroll
  for(int am=0;am<2;am++){
    int rloc = wm*32 + am*16 + qr;
    int rowa = (int)row0 + rloc;
#pragma unroll
    for(int bn=0;bn<8;bn++){
      int cg = nb + wn*64 + bn*8 + 2*ql;
      size_t o0 = (size_t)rowa*HD + cg, o1 = o0 + 8*HD;
      float v0=acc[am][bn][0], v1=acc[am][bn][1], v2=acc[am][bn][2], v3=acc[am][bn][3];
      if(mi==0){
        float b0=sbk[cg], b1=sbk[cg+1];
        *(float2*)(g_ksw+o0)=make_float2(v0+b0,v1+b1);
        *(float2*)(g_ksw+o1)=make_float2(v2+b0,v3+b1);
      } else if(mi==1){
        *(float2*)(g_mq+o0)=make_float2(v0,v1);
        *(float2*)(g_mq+o1)=make_float2(v2,v3);
      } else if(mi==2){
        *(unsigned*)(g_kt+o0) = pk2(v0*ISD, v1*ISD);
        *(unsigned*)(g_kt+o1) = pk2(v2*ISD, v3*ISD);
      } else if(mi==3){
        int i = ibase + rloc;
        size_t d0 = ((size_t)(nn*8 + (cg>>5))*32 + (cg&31))*Ll + i;
        g_vT[d0]      = __float2half_rn(v0);
        g_vT[d0+Ll]   = __float2half_rn(v1);
        g_vT[d0+8]    = __float2half_rn(v2);
        g_vT[d0+Ll+8] = __float2half_rn(v3);
      } else {
        float b0=bg[cg], b1=bg[cg+1];
        *(float2*)(g_gate+o0)=make_float2(1.f/(1.f+expf(-(v0+b0))), 1.f/(1.f+expf(-(v1+b1))));
        *(float2*)(g_gate+o1)=make_float2(1.f/(1.f+expf(-(v2+b0))), 1.f/(1.f+expf(-(v3+b1))));
      }
    }
  }
}

// ---- K3: pair LN + bias projection via tf32 MMA ------------------------------
#define PB_SMEM ((128*132 + 1024)*4)
__global__ __launch_bounds__(256) void k_pbmm(const float* __restrict__ pair,
    const float* __restrict__ lnpg, const float* __restrict__ lnpb,
    const float* __restrict__ wb){
  extern __shared__ char dsmc[];
  unsigned* dsm = (unsigned*)dsmc;
  unsigned (*sA)[132] = (unsigned(*)[132])dsm;
  unsigned* swb = dsm + 128*132;
  const uint32_t sbA = s2u(dsm);
  const int t = threadIdx.x;
  const size_t p0 = (size_t)blockIdx.x*128;
  for(int u=t; u<1024; u+=256) swb[u] = f2tf(wb[u]);
  {
    int row = t>>1, half = t&1;
    const float* rp = pair + (p0+row)*128 + half*64;
    float s=0.f, ss=0.f;
#pragma unroll
    for(int f=0;f<16;f++){ float4 x = *(const float4*)(rp+f*4);
      s += x.x+x.y+x.z+x.w; ss += x.x*x.x+x.y*x.y+x.z*x.z+x.w*x.w; }
    s  += __shfl_xor_sync(0xffffffffu, s, 1);
    ss += __shfl_xor_sync(0xffffffffu, ss, 1);
    float mean = s*(1.f/128.f), inv = rsqrtf(ss*(1.f/128.f)-mean*mean+1e-5f);
#pragma unroll
    for(int f=0;f<16;f++){
      int c = half*64 + f*4;
      float4 x = *(const float4*)(pair + (p0+row)*128 + c);
      sA[row][c  ] = f2tf((x.x-mean)*inv*lnpg[c  ]+lnpb[c  ]);
      sA[row][c+1] = f2tf((x.y-mean)*inv*lnpg[c+1]+lnpb[c+1]);
      sA[row][c+2] = f2tf((x.z-mean)*inv*lnpg[c+2]+lnpb[c+2]);
      sA[row][c+3] = f2tf((x.w-mean)*inv*lnpg[c+3]+lnpb[c+3]);
    }
  }
  __syncthreads();
  const int w = t>>5, lane = t&31;
  const int qr = lane>>2, ql = lane&3;
  const int R = w*16;
  const uint32_t aoff = sbA + ((R + (lane&15))*132 + ((lane>>4)<<2))*4;
  float acc[4] = {0.f,0.f,0.f,0.f};
#pragma unroll
  for(int ks=0; ks<16; ks++){
    unsigned a[4], b[2];
    ldsm4(a, aoff + ks*32);
    b[0] = swb[(ks*8+ql  )*8 + qr];
    b[1] = swb[(ks*8+ql+4)*8 + qr];
    mma_tf32(acc, a, b);
  }
  size_t p = p0 + R + qr;
  int h0 = 2*ql, h1 = 2*ql+1;
  g_pb[(size_t)h0*LLc + p]     = acc[0];
  g_pb[(size_t)h1*LLc + p]     = acc[1];
  g_pb[(size_t)h0*LLc + p + 8] = acc[2];
  g_pb[(size_t)h1*LLc + p + 8] = acc[3];
}

// ---- K2: seq-weight logits + softmax over n ----------------------------------
__global__ __launch_bounds__(256) void k_swl(){
  __shared__ float sq[256]; __shared__ float sL[256][9];
  __shared__ float smx[8], srs[8];
  int i = blockIdx.x, t = threadIdx.x;
  sq[t] = g_qsw[i*HD+t];
  __syncthreads();
  const float* kr = g_ksw + ((size_t)t*Ll + i)*HD;
  float lg[8];
#pragma unroll
  for(int h=0;h<8;h++){
    float s=0.f;
#pragma unroll
    for(int f=0;f<8;f++){
      float4 kx = *(const float4*)(kr + h*32 + f*4);
      int c = h*32+f*4;
      s += kx.x*sq[c]+kx.y*sq[c+1]+kx.z*sq[c+2]+kx.w*sq[c+3];
    }
    lg[h]=s; sL[t][h]=s;
  }
  __syncthreads();
  { int w=t>>5, lane=t&31;
    float mx=-3.4e38f;
#pragma unroll
    for(int e=0;e<8;e++) mx=fmaxf(mx, sL[lane*8+e][w]);
    mx=warpMax(mx);
    float s=0.f;
#pragma unroll
    for(int e=0;e<8;e++) s+=expf(sL[lane*8+e][w]-mx);
    s=warpSum(s);
    if(lane==0){ smx[w]=mx; srs[w]=1.f/s; } }
  __syncthreads();
  size_t o = ((size_t)t*Ll + i)*Hh;
#pragma unroll
  for(int h=0;h<8;h++) g_sw[o+h] = expf(lg[h]-smx[h])*srs[h];
}

// ---- K_qs: Q * seqweight -> fp16 ---------------------------------------------
__global__ __launch_bounds__(256) void k_qs(){
  int u = blockIdx.x*256 + threadIdx.x;
  int row = u>>6, c4 = (u&63)*4;
  float sv = g_sw[(size_t)row*Hh + (c4>>5)];
  float4 x = *(const float4*)(g_mq + (size_t)row*HD + c4);
  uint2 o;
  o.x = pk2(x.x*sv, x.y*sv);
  o.y = pk2(x.z*sv, x.w*sv);
  *(uint2*)(g_qst + (size_t)row*HD + c4) = o;
}

// ---- K4: attn logits fp16, 128x64 tile, split-K over n (2 halves) ------------
#define ATTN_SMEM (2*27648)
__global__ __launch_bounds__(256) void k_attn(){
  extern __shared__ char dsm[];
  const uint32_t sb = s2u(dsm);
  const int t = threadIdx.x, h = blockIdx.z, i0 = blockIdx.x*128;
  const int jy = blockIdx.y;
  const int j0 = (jy>>1)*64;
  const int nh = (jy&1)*128;              // n half: [nh, nh+128)
  const int w = t>>5, lane = t&31;
  const int wm = w>>1, wn = w&1;
  const int qr = lane>>2, ql = lane&3;
  const uint32_t aLn = ((wm*32 + (lane&15))*72 + ((lane>>4)<<3))*2;
  const uint32_t bLn = ((wn*32 + (lane&7) + ((lane&16)>>1))*72 + (((lane>>3)&1)<<3))*2;
  float acc[2][4][4];
#pragma unroll
  for(int am=0;am<2;am++)
#pragma unroll
    for(int bn=0;bn<4;bn++)
#pragma unroll
      for(int e=0;e<4;e++) acc[am][bn][e]=0.f;

#pragma unroll
  for(int c=0;c<4;c++){ int u=c*256+t, r=u>>3, cu=u&7;
    int nsel = cu>>2, d0 = (cu&3)*8;
    cpa16(sb + r*144 + cu*16, g_qst + ((size_t)(nh+nsel)*Ll + i0 + r)*HD + h*32 + d0); }
#pragma unroll
  for(int c=0;c<2;c++){ int u=c*256+t, r=u>>3, cu=u&7;
    int nsel = cu>>2, d0 = (cu&3)*8;
    cpa16(sb + 18432 + r*144 + cu*16, g_kt + ((size_t)(nh+nsel)*Ll + j0 + r)*HD + h*32 + d0); }
  CPC();
  for(int it=0; it<64; it++){
    if(it+1<64){
      uint32_t dst = sb + ((it+1)&1)*27648;
      int nbase = nh + 2*(it+1);
#pragma unroll
      for(int c=0;c<4;c++){ int u=c*256+t, r=u>>3, cu=u&7;
        int nsel = cu>>2, d0 = (cu&3)*8;
        cpa16(dst + r*144 + cu*16, g_qst + ((size_t)(nbase+nsel)*Ll + i0 + r)*HD + h*32 + d0); }
#pragma unroll
      for(int c=0;c<2;c++){ int u=c*256+t, r=u>>3, cu=u&7;
        int nsel = cu>>2, d0 = (cu&3)*8;
        cpa16(dst + 18432 + r*144 + cu*16, g_kt + ((size_t)(nbase+nsel)*Ll + j0 + r)*HD + h*32 + d0); }
      CPC(); CPW1();
    } else CPW0();
    __syncthreads();
    const uint32_t st = sb + (it&1)*27648;
    const uint32_t bst = st + 18432;
#pragma unroll
    for(int ks=0;ks<4;ks++){
      const uint32_t kb = ks*32;
      unsigned a0[4], a1[4], bf0[4], bf1[4];
      ldsm4(a0, st + aLn + kb);
      ldsm4(a1, st + aLn + 16*144 + kb);
      ldsm4(bf0, bst + bLn + kb);
      ldsm4(bf1, bst + bLn + 16*144 + kb);
      mma_f16(acc[0][0], a0, bf0);  mma_f16(acc[0][1], a0, bf0+2);
      mma_f16(acc[0][2], a0, bf1);  mma_f16(acc[0][3], a0, bf1+2);
      mma_f16(acc[1][0], a1, bf0);  mma_f16(acc[1][1], a1, bf0+2);
      mma_f16(acc[1][2], a1, bf1);  mma_f16(acc[1][3], a1, bf1+2);
    }
    __syncthreads();
  }
  float* dst = g_attn + (size_t)(jy&1)*HLL + (size_t)h*LLc;
#pragma unroll
  for(int am=0;am<2;am++){
    int i = i0 + wm*32 + am*16 + qr;
#pragma unroll
    for(int bn=0;bn<4;bn++){
      int j = j0 + wn*32 + bn*8 + 2*ql;
      size_t o = (size_t)i*Ll + j;
      *(float2*)(dst+o) = make_float2(acc[am][bn][0], acc[am][bn][1]);
      size_t o2 = o + (size_t)8*Ll;
      *(float2*)(dst+o2) = make_float2(acc[am][bn][2], acc[am][bn][3]);
    }
  }
}

// ---- K5: combine partials + pair bias + softmax over j -> fp16 probs ---------
__global__ void k_attnsoftmax(){
  int b = blockIdx.x, h = b/Ll, i = b%Ll, t = threadIdx.x;
  __shared__ float red[32];
  size_t base = (size_t)h*LLc + (size_t)i*Ll;
  float x0 = g_attn[base+t]     + g_attn[HLL+base+t]     + g_pb[base+t];
  float x1 = g_attn[base+128+t] + g_attn[HLL+base+128+t] + g_pb[base+128+t];
  float x2 = g_attn[base+256+t] + g_attn[HLL+base+256+t] + g_pb[base+256+t];
  float mx = blockMax(fmaxf(x0,fmaxf(x1,x2)), red, 4);
  float e0=expf(x0-mx), e1=expf(x1-mx), e2=expf(x2-mx);
  float s = blockSum(e0+e1+e2, red, 4);
  float inv = 1.f/s;
  g_pt[base+t]     = __float2half_rn(e0*inv);
  g_pt[base+128+t] = __float2half_rn(e1*inv);
  g_pt[base+256+t] = __float2half_rn(e2*inv);
}

// ---- K6: P @ V fp16, epilogue fuses gate, writes fp16 g_og -------------------
#define PV_SMEM (2*20480)
__global__ __launch_bounds__(256) void k_pv(){
  extern __shared__ char dsm[];
  const uint32_t sb = s2u(dsm);
  const int t = threadIdx.x, h = blockIdx.z, i0 = blockIdx.x*128, n0 = blockIdx.y*4;
  const int w = t>>5, lane = t&31;
  const int wm = w>>1, wn = w&1;
  const int qr = lane>>2, ql = lane&3;
  const uint32_t aLn = ((wm*32 + (lane&15))*40 + ((lane>>4)<<3))*2;
  const uint32_t bLn = ((wn*64 + (lane&7) + ((lane&16)>>1))*40 + (((lane>>3)&1)<<3))*2;
  float acc[2][8][4];
#pragma unroll
  for(int am=0;am<2;am++)
#pragma unroll
    for(int bn=0;bn<8;bn++)
#pragma unroll
      for(int e=0;e<4;e++) acc[am][bn][e]=0.f;

  const size_t aBase = (size_t)h*LLc + (size_t)i0*Ll;
#pragma unroll
  for(int c=0;c<2;c++){ int u=c*256+t, r=u>>2, cu=u&3;
    cpa16(sb + r*80 + cu*16, g_pt + aBase + (size_t)r*Ll + cu*8); }
#pragma unroll
  for(int c=0;c<2;c++){ int u=c*256+t, rr=u>>2, cu=u&3;
    size_t grow = ((size_t)(n0+(rr>>5))*8 + h)*32 + (rr&31);
    cpa16(sb + 10240 + rr*80 + cu*16, g_vT + grow*Ll + cu*8); }
  CPC();
  for(int jc=0;jc<12;jc++){
    if(jc+1<12){
      int j1 = (jc+1)*32;
      uint32_t dst = sb + ((jc+1)&1)*20480;
#pragma unroll
      for(int c=0;c<2;c++){ int u=c*256+t, r=u>>2, cu=u&3;
        cpa16(dst + r*80 + cu*16, g_pt + aBase + (size_t)r*Ll + j1 + cu*8); }
#pragma unroll
      for(int c=0;c<2;c++){ int u=c*256+t, rr=u>>2, cu=u&3;
        size_t grow = ((size_t)(n0+(rr>>5))*8 + h)*32 + (rr&31);
        cpa16(dst + 10240 + rr*80 + cu*16, g_vT + grow*Ll + j1 + cu*8); }
      CPC(); CPW1();
    } else CPW0();
    __syncthreads();
    const uint32_t st = sb + (jc&1)*20480;
    const uint32_t bst = st + 10240;
#pragma unroll
    for(int ks=0;ks<2;ks++){
      const uint32_t kb = ks*32;
      unsigned a0[4], a1[4], bf[4][4];
      ldsm4(a0, st + aLn + kb);
      ldsm4(a1, st + aLn + 16*80 + kb);
#pragma unroll
      for(int q=0;q<4;q++) ldsm4(bf[q], bst + bLn + q*16*80 + kb);
#pragma unroll
      for(int bn=0;bn<8;bn++){
        mma_f16(acc[0][bn], a0, bf[bn>>1] + 2*(bn&1));
        mma_f16(acc[1][bn], a1, bf[bn>>1] + 2*(bn&1));
      }
    }
    __syncthreads();
  }
#pragma unroll
  for(int am=0;am<2;am++){
    int i = i0 + wm*32 + am*16 + qr;
#pragma unroll
    for(int bn=0;bn<8;bn++){
      int col = wn*64 + bn*8 + 2*ql;
      int nv = col>>5, dd = col&31;
      size_t o = ((size_t)(n0+nv)*Ll + i)*HD + h*Dd + dd;
      float2 ga = *(const float2*)(g_gate+o);
      *(unsigned*)(g_og+o) = pk2(acc[am][bn][0]*ga.x, acc[am][bn][1]*ga.y);
      size_t o2 = o + (size_t)8*HD;
      float2 gb = *(const float2*)(g_gate+o2);
      *(unsigned*)(g_og+o2) = pk2(acc[am][bn][2]*gb.x, acc[am][bn][3]*gb.y);
    }
  }
}

// ---- K7: out projection fp16, CTA 128x128, warp 32x64, K-chunk 64 ------------
__global__ __launch_bounds__(256) void k_out(const float* __restrict__ bo,
                                             float* __restrict__ out){
  extern __shared__ char dsm[];
  const uint32_t sb = s2u(dsm);
  const int t = threadIdx.x;
  const size_t row0 = (size_t)blockIdx.y*128;
  const int nb = blockIdx.x*128;
  const __half* Bsrc = g_wt + ((size_t)5*256 + nb)*256;

  const int w = t>>5, lane = t&31;
  const int wm = w>>1, wn = w&1;
  const int qr = lane>>2, ql = lane&3;
  const uint32_t aLn = ((wm*32 + (lane&15))*72 + ((lane>>4)<<3))*2;
  const uint32_t bLn = ((wn*64 + (lane&7) + ((lane&16)>>1))*72 + (((lane>>3)&1)<<3))*2;

#pragma unroll
  for(int c=0;c<4;c++){ int u=c*256+t, r=u>>3, cu=u&7;
    cpa16(sb + r*144 + cu*16, g_og + (row0+r)*HD + cu*8); }
#pragma unroll
  for(int c=0;c<4;c++){ int u=c*256+t, r=u>>3, cu=u&7;
    cpa16(sb + 18432 + r*144 + cu*16, Bsrc + (size_t)r*256 + cu*8); }
  CPC();

  float acc[2][8][4];
#pragma unroll
  for(int am=0;am<2;am++)
#pragma unroll
    for(int bn=0;bn<8;bn++)
#pragma unroll
      for(int e=0;e<4;e++) acc[am][bn][e]=0.f;

  for(int kc=0;kc<4;kc++){
    if(kc+1<4){
      int k1 = (kc+1)*64;
      uint32_t dst = sb + ((kc+1)&1)*36864;
#pragma unroll
      for(int c=0;c<4;c++){ int u=c*256+t, r=u>>3, cu=u&7;
        cpa16(dst + r*144 + cu*16, g_og + (row0+r)*HD + k1 + cu*8); }
#pragma unroll
      for(int c=0;c<4;c++){ int u=c*256+t, r=u>>3, cu=u&7;
        cpa16(dst + 18432 + r*144 + cu*16, Bsrc + (size_t)r*256 + k1 + cu*8); }
      CPC(); CPW1();
    } else CPW0();
    __syncthreads();
    const uint32_t st = sb + (kc&1)*36864;
    const uint32_t bst = st + 18432;
#pragma unroll
    for(int ks=0;ks<4;ks++){
      const uint32_t kb = ks*32;
      unsigned a0[4], a1[4], bf[4][4];
      ldsm4(a0, st + aLn + kb);
      ldsm4(a1, st + aLn + 16*144 + kb);
#pragma unroll
      for(int q=0;q<4;q++) ldsm4(bf[q], bst + bLn + q*16*144 + kb);
#pragma unroll
      for(int bn=0;bn<8;bn++){
        mma_f16(acc[0][bn], a0, bf[bn>>1] + 2*(bn&1));
        mma_f16(acc[1][bn], a1, bf[bn>>1] + 2*(bn&1));
      }
    }
    __syncthreads();
  }
#pragma unroll
  for(int am=0;am<2;am++){
    int rowa = (int)row0 + wm*32 + am*16 + qr;
#pragma unroll
    for(int bn=0;bn<8;bn++){
      int cg = nb + wn*64 + bn*8 + 2*ql;
      float2 b2 = *(const float2*)(bo + cg);
      *(float2*)(out + (size_t)rowa*HD + cg) = make_float2(acc[am][bn][0]+b2.x, acc[am][bn][1]+b2.y);
      *(float2*)(out + (size_t)(rowa+8)*HD + cg) = make_float2(acc[am][bn][2]+b2.x, acc[am][bn][3]+b2.y);
    }
  }
}

// ---- launch ------------------------------------------------------------------
extern "C" void kernel_launch(void* const* d_in, const int* in_sizes, int n_in,
                              void* d_out, int out_size){
  const float* msa      = (const float*)d_in[0];
  const float* pair     = (const float*)d_in[1];
  const float* ln_msa_g = (const float*)d_in[2];
  const float* ln_msa_b = (const float*)d_in[3];
  const float* ln_pair_g= (const float*)d_in[4];
  const float* ln_pair_b= (const float*)d_in[5];
  const float* sw_wq    = (const float*)d_in[6];
  const float* sw_bq    = (const float*)d_in[7];
  const float* sw_wk    = (const float*)d_in[8];
  const float* sw_bk    = (const float*)d_in[9];
  const float* wq       = (const float*)d_in[10];
  const float* wk       = (const float*)d_in[11];
  const float* wv       = (const float*)d_in[12];
  const float* wb       = (const float*)d_in[13];
  const float* wg       = (const float*)d_in[14];
  const float* bg       = (const float*)d_in[15];
  const float* wo       = (const float*)d_in[16];
  const float* bo       = (const float*)d_in[17];
  float* out = (float*)d_out;

  cudaFuncSetAttribute(k_proj, cudaFuncAttributeMaxDynamicSharedMemorySize, PROJ_SMEM);
  cudaFuncSetAttribute(k_attn, cudaFuncAttributeMaxDynamicSharedMemorySize, ATTN_SMEM);
  cudaFuncSetAttribute(k_pv,   cudaFuncAttributeMaxDynamicSharedMemorySize, PV_SMEM);
  cudaFuncSetAttribute(k_out,  cudaFuncAttributeMaxDynamicSharedMemorySize, PROJ_SMEM);
  cudaFuncSetAttribute(k_pbmm, cudaFuncAttributeMaxDynamicSharedMemorySize, PB_SMEM);

  k_prep<<<6*256, 256>>>(sw_wk, wq, wk, wv, wg, wo);          // 1
  k_qsw<<<Ll, 256>>>(msa, ln_msa_g, ln_msa_b, sw_wq, sw_bq);  // 2
  k_ln<<<NL/32, 256>>>(msa, ln_msa_g, ln_msa_b);              // 3
  k_proj<<<dim3(10, NL/128), 256, PROJ_SMEM>>>(sw_bk, bg);    // 4 (ncu slot)
  k_pbmm<<<LLc/128, 256, PB_SMEM>>>(pair, ln_pair_g, ln_pair_b, wb); // 5
  k_swl<<<Ll, 256>>>();                                       // 6
  k_qs<<<NL*HD/1024, 256>>>();                                // 7
  k_attn<<<dim3(3,12,8), 256, ATTN_SMEM>>>();                 // 8 (split-K n)
  k_attnsoftmax<<<Hh*Ll, 128>>>();                            // 9
  k_pv<<<dim3(3,64,8), 256, PV_SMEM>>>();                     // 10
  k_out<<<dim3(2, NL/128), 256, PROJ_SMEM>>>(bo, out);        // 11
}

// round 16
// speedup vs baseline: 1.4783x; 1.4783x over previous
#include <cuda_runtime.h>
#include <cuda_fp16.h>
#include <math.h>
#include <stdint.h>

#define Nn 256
#define Ll 384
#define Hh 8
#define Dd 32
#define HD 256
#define NL (Nn*Ll)
#define LLc (Ll*Ll)
#define ISD 0.17677669529663687f

// fp32 scratch
__device__ float g_qsw[Ll*HD];
__device__ float g_ksw[NL*HD];
__device__ float g_mq[NL*HD];
__device__ float g_gate[NL*HD];
__device__ float g_sw[NL*Hh];
__device__ float g_pb[Hh*LLc];
__device__ float g_attn[Hh*LLc];
// fp16 operands
__device__ __half g_at[NL*HD];
__device__ __half g_wt[6*256*256];
__device__ __half g_kt[NL*HD];
__device__ __half g_qst[NL*HD];
__device__ __half g_pt[Hh*LLc];
__device__ __half g_vT[NL*HD];
__device__ __half g_og[NL*HD];

// ---------------- helpers ----------------------------------------------------
__device__ __forceinline__ unsigned f2tf(float x){
  unsigned u; asm("cvt.rna.tf32.f32 %0, %1;" : "=r"(u) : "f"(x)); return u;
}
__device__ __forceinline__ unsigned pk2(float x, float y){
  __half2 h = __floats2half2_rn(x, y);
  return *(unsigned*)&h;
}
__device__ __forceinline__ void mma_f16(float c[4], const unsigned a[4], const unsigned b[2]){
  asm volatile("mma.sync.aligned.m16n8k16.row.col.f32.f16.f16.f32 "
    "{%0,%1,%2,%3},{%4,%5,%6,%7},{%8,%9},{%0,%1,%2,%3};"
    : "+f"(c[0]),"+f"(c[1]),"+f"(c[2]),"+f"(c[3])
    : "r"(a[0]),"r"(a[1]),"r"(a[2]),"r"(a[3]),"r"(b[0]),"r"(b[1]));
}
__device__ __forceinline__ void mma_tf32(float c[4], const unsigned a[4], const unsigned b[2]){
  asm volatile("mma.sync.aligned.m16n8k8.row.col.f32.tf32.tf32.f32 "
    "{%0,%1,%2,%3},{%4,%5,%6,%7},{%8,%9},{%0,%1,%2,%3};"
    : "+f"(c[0]),"+f"(c[1]),"+f"(c[2]),"+f"(c[3])
    : "r"(a[0]),"r"(a[1]),"r"(a[2]),"r"(a[3]),"r"(b[0]),"r"(b[1]));
}
__device__ __forceinline__ void ldsm4(unsigned r[4], uint32_t a){
  asm volatile("ldmatrix.sync.aligned.m8n8.x4.shared.b16 {%0,%1,%2,%3}, [%4];"
    : "=r"(r[0]),"=r"(r[1]),"=r"(r[2]),"=r"(r[3]) : "r"(a));
}
__device__ __forceinline__ uint32_t s2u(const void* p){
  uint32_t a; asm("{ .reg .u64 t; cvta.to.shared.u64 t, %1; cvt.u32.u64 %0, t; }" : "=r"(a) : "l"(p)); return a;
}
__device__ __forceinline__ void cpa16(uint32_t s, const void* g){
  asm volatile("cp.async.cg.shared.global [%0], [%1], 16;" :: "r"(s), "l"(g));
}
#define CPC() asm volatile("cp.async.commit_group;" ::: "memory")
#define CPW1() asm volatile("cp.async.wait_group 1;" ::: "memory")
#define CPW0() asm volatile("cp.async.wait_group 0;" ::: "memory")

__device__ __forceinline__ float warpSum(float v){
#pragma unroll
  for(int o=16;o;o>>=1) v += __shfl_xor_sync(0xffffffffu, v, o);
  return v;
}
__device__ __forceinline__ float warpMax(float v){
#pragma unroll
  for(int o=16;o;o>>=1) v = fmaxf(v, __shfl_xor_sync(0xffffffffu, v, o));
  return v;
}
__device__ __forceinline__ float blockSum(float v, float* red, int nw){
  int t=threadIdx.x; v=warpSum(v);
  if((t&31)==0) red[t>>5]=v;
  __syncthreads();
  float s=0.f;
  if(t<32){ s=(t<nw)?red[t]:0.f; s=warpSum(s); if(t==0) red[0]=s; }
  __syncthreads(); s=red[0]; __syncthreads(); return s;
}
__device__ __forceinline__ float blockMax(float v, float* red, int nw){
  int t=threadIdx.x; v=warpMax(v);
  if((t&31)==0) red[t>>5]=v;
  __syncthreads();
  float s=-3.4e38f;
  if(t<32){ s=(t<nw)?red[t]:-3.4e38f; s=warpMax(s); if(t==0) red[0]=s; }
  __syncthreads(); s=red[0]; __syncthreads(); return s;
}

// ---- prep: convert+transpose 6 weight mats to fp16 [mat][n][k] ---------------
__global__ void k_prep(const float* __restrict__ w0, const float* __restrict__ w1,
                       const float* __restrict__ w2, const float* __restrict__ w3,
                       const float* __restrict__ w4, const float* __restrict__ w5){
  int bid = blockIdx.x, t = threadIdx.x;
  int mat = bid>>8, n = bid&255;
  const float* W = (mat==0)?w0:(mat==1)?w1:(mat==2)?w2:(mat==3)?w3:(mat==4)?w4:w5;
  g_wt[(size_t)bid*256 + t] = __float2half_rn(W[t*256 + n]);
}

// ---- K_ln: LN(msa) -> fp16 g_at ----------------------------------------------
__global__ __launch_bounds__(256) void k_ln(const float* __restrict__ msa,
    const float* __restrict__ lng, const float* __restrict__ lnb){
  size_t r = (size_t)blockIdx.x*32 + (threadIdx.x>>3);
  int q = threadIdx.x&7;
  const float* rp = msa + r*HD + q*32;
  float4 xv[8];
  float s=0.f, ss=0.f;
#pragma unroll
  for(int f=0;f<8;f++){
    xv[f] = *(const float4*)(rp + f*4);
    s  += xv[f].x+xv[f].y+xv[f].z+xv[f].w;
    ss += xv[f].x*xv[f].x+xv[f].y*xv[f].y+xv[f].z*xv[f].z+xv[f].w*xv[f].w;
  }
#pragma unroll
  for(int o=1;o<8;o<<=1){ s += __shfl_xor_sync(0xffffffffu,s,o); ss += __shfl_xor_sync(0xffffffffu,ss,o); }
  float mean = s*(1.f/HD), inv = rsqrtf(ss*(1.f/HD)-mean*mean+1e-5f);
#pragma unroll
  for(int f=0;f<8;f++){
    int c = q*32 + f*4;
    uint2 o;
    o.x = pk2((xv[f].x-mean)*inv*lng[c  ]+lnb[c  ], (xv[f].y-mean)*inv*lng[c+1]+lnb[c+1]);
    o.y = pk2((xv[f].z-mean)*inv*lng[c+2]+lnb[c+2], (xv[f].w-mean)*inv*lng[c+3]+lnb[c+3]);
    *(uint2*)(g_at + r*HD + c) = o;
  }
}

// ---- K0: qsw row 0 -----------------------------------------------------------
__global__ void k_qsw(const float* __restrict__ msa, const float* __restrict__ lng,
                      const float* __restrict__ lnb, const float* __restrict__ swq,
                      const float* __restrict__ sbq){
  int i = blockIdx.x, t = threadIdx.x;
  __shared__ float sm[HD]; __shared__ float red[32];
  float x = msa[(size_t)i*HD + t];
  float mean = blockSum(x, red, 8)*(1.f/HD);
  float d = x-mean;
  float var = blockSum(d*d, red, 8)*(1.f/HD);
  sm[t] = d*rsqrtf(var+1e-5f)*lng[t]+lnb[t];
  __syncthreads();
  float acc = sbq[t];
#pragma unroll 8
  for(int r=0;r<HD;r++) acc += sm[r]*swq[r*HD+t];
  g_qsw[i*HD+t] = acc*ISD;
}

// ---- K1: 5 projections fp16, CTA 128x128, warp 32x64, K-chunk 64 -------------
#define PROJ_SMEM (2*36864)
__global__ __launch_bounds__(256) void k_proj(const float* __restrict__ sbk,
                                              const float* __restrict__ bg){
  extern __shared__ char dsm[];
  const uint32_t sb = s2u(dsm);
  const int t = threadIdx.x;
  const size_t row0 = (size_t)blockIdx.y*128;
  const int by = blockIdx.x;                 // 0..9
  const int mi = by>>1, nb = (by&1)*128;
  const int nn = (int)(row0/Ll);
  const int ibase = (int)(row0%Ll);
  const __half* Bsrc = g_wt + ((size_t)mi*256 + nb)*256;

  const int w = t>>5, lane = t&31;
  const int wm = w>>1, wn = w&1;
  const int qr = lane>>2, ql = lane&3;
  const uint32_t aLn = ((wm*32 + (lane&15))*72 + ((lane>>4)<<3))*2;
  const uint32_t bLn = ((wn*64 + (lane&7) + ((lane&16)>>1))*72 + (((lane>>3)&1)<<3))*2;

#pragma unroll
  for(int c=0;c<4;c++){ int u=c*256+t, r=u>>3, cu=u&7;
    cpa16(sb + r*144 + cu*16, g_at + (row0+r)*HD + cu*8); }
#pragma unroll
  for(int c=0;c<4;c++){ int u=c*256+t, r=u>>3, cu=u&7;
    cpa16(sb + 18432 + r*144 + cu*16, Bsrc + (size_t)r*256 + cu*8); }
  CPC();

  float acc[2][8][4];
#pragma unroll
  for(int am=0;am<2;am++)
#pragma unroll
    for(int bn=0;bn<8;bn++)
#pragma unroll
      for(int e=0;e<4;e++) acc[am][bn][e]=0.f;

  for(int kc=0;kc<4;kc++){
    if(kc+1<4){
      int k1 = (kc+1)*64;
      uint32_t dst = sb + ((kc+1)&1)*36864;
#pragma unroll
      for(int c=0;c<4;c++){ int u=c*256+t, r=u>>3, cu=u&7;
        cpa16(dst + r*144 + cu*16, g_at + (row0+r)*HD + k1 + cu*8); }
#pragma unroll
      for(int c=0;c<4;c++){ int u=c*256+t, r=u>>3, cu=u&7;
        cpa16(dst + 18432 + r*144 + cu*16, Bsrc + (size_t)r*256 + k1 + cu*8); }
      CPC(); CPW1();
    } else CPW0();
    __syncthreads();
    const uint32_t st = sb + (kc&1)*36864;
    const uint32_t bst = st + 18432;
#pragma unroll
    for(int ks=0;ks<4;ks++){
      const uint32_t kb = ks*32;
      unsigned a0[4], a1[4], bf[4][4];
      ldsm4(a0, st + aLn + kb);
      ldsm4(a1, st + aLn + 16*144 + kb);
#pragma unroll
      for(int q=0;q<4;q++) ldsm4(bf[q], bst + bLn + q*16*144 + kb);
#pragma unroll
      for(int bn=0;bn<8;bn++){
        mma_f16(acc[0][bn], a0, bf[bn>>1] + 2*(bn&1));
        mma_f16(acc[1][bn], a1, bf[bn>>1] + 2*(bn&1));
      }
    }
    __syncthreads();
  }
#pragma unroll
  for(int am=0;am<2;am++){
    int rloc = wm*32 + am*16 + qr;
    int rowa = (int)row0 + rloc;
#pragma unroll
    for(int bn=0;bn<8;bn++){
      int cg = nb + wn*64 + bn*8 + 2*ql;
      size_t o0 = (size_t)rowa*HD + cg, o1 = o0 + 8*HD;
      float v0=acc[am][bn][0], v1=acc[am][bn][1], v2=acc[am][bn][2], v3=acc[am][bn][3];
      if(mi==0){
        float b0=sbk[cg], b1=sbk[cg+1];
        *(float2*)(g_ksw+o0)=make_float2(v0+b0,v1+b1);
        *(float2*)(g_ksw+o1)=make_float2(v2+b0,v3+b1);
      } else if(mi==1){
        *(float2*)(g_mq+o0)=make_float2(v0,v1);
        *(float2*)(g_mq+o1)=make_float2(v2,v3);
      } else if(mi==2){
        *(unsigned*)(g_kt+o0) = pk2(v0*ISD, v1*ISD);
        *(unsigned*)(g_kt+o1) = pk2(v2*ISD, v3*ISD);
      } else if(mi==3){
        int i = ibase + rloc;
        size_t d0 = ((size_t)(nn*8 + (cg>>5))*32 + (cg&31))*Ll + i;
        g_vT[d0]      = __float2half_rn(v0);
        g_vT[d0+Ll]   = __float2half_rn(v1);
        g_vT[d0+8]    = __float2half_rn(v2);
        g_vT[d0+Ll+8] = __float2half_rn(v3);
      } else {
        float b0=bg[cg], b1=bg[cg+1];
        *(float2*)(g_gate+o0)=make_float2(1.f/(1.f+expf(-(v0+b0))), 1.f/(1.f+expf(-(v1+b1))));
        *(float2*)(g_gate+o1)=make_float2(1.f/(1.f+expf(-(v2+b0))), 1.f/(1.f+expf(-(v3+b1))));
      }
    }
  }
}

// ---- K3: pair LN + bias projection via tf32 MMA ------------------------------
#define PB_SMEM ((128*132 + 1024)*4)
__global__ __launch_bounds__(256) void k_pbmm(const float* __restrict__ pair,
    const float* __restrict__ lnpg, const float* __restrict__ lnpb,
    const float* __restrict__ wb){
  extern __shared__ char dsmc[];
  unsigned* dsm = (unsigned*)dsmc;
  unsigned (*sA)[132] = (unsigned(*)[132])dsm;
  unsigned* swb = dsm + 128*132;
  const uint32_t sbA = s2u(dsm);
  const int t = threadIdx.x;
  const size_t p0 = (size_t)blockIdx.x*128;
  for(int u=t; u<1024; u+=256) swb[u] = f2tf(wb[u]);
  {
    int row = t>>1, half = t&1;
    const float* rp = pair + (p0+row)*128 + half*64;
    float s=0.f, ss=0.f;
#pragma unroll
    for(int f=0;f<16;f++){ float4 x = *(const float4*)(rp+f*4);
      s += x.x+x.y+x.z+x.w; ss += x.x*x.x+x.y*x.y+x.z*x.z+x.w*x.w; }
    s  += __shfl_xor_sync(0xffffffffu, s, 1);
    ss += __shfl_xor_sync(0xffffffffu, ss, 1);
    float mean = s*(1.f/128.f), inv = rsqrtf(ss*(1.f/128.f)-mean*mean+1e-5f);
#pragma unroll
    for(int f=0;f<16;f++){
      int c = half*64 + f*4;
      float4 x = *(const float4*)(pair + (p0+row)*128 + c);
      sA[row][c  ] = f2tf((x.x-mean)*inv*lnpg[c  ]+lnpb[c  ]);
      sA[row][c+1] = f2tf((x.y-mean)*inv*lnpg[c+1]+lnpb[c+1]);
      sA[row][c+2] = f2tf((x.z-mean)*inv*lnpg[c+2]+lnpb[c+2]);
      sA[row][c+3] = f2tf((x.w-mean)*inv*lnpg[c+3]+lnpb[c+3]);
    }
  }
  __syncthreads();
  const int w = t>>5, lane = t&31;
  const int qr = lane>>2, ql = lane&3;
  const int R = w*16;
  const uint32_t aoff = sbA + ((R + (lane&15))*132 + ((lane>>4)<<2))*4;
  float acc[4] = {0.f,0.f,0.f,0.f};
#pragma unroll
  for(int ks=0; ks<16; ks++){
    unsigned a[4], b[2];
    ldsm4(a, aoff + ks*32);
    b[0] = swb[(ks*8+ql  )*8 + qr];
    b[1] = swb[(ks*8+ql+4)*8 + qr];
    mma_tf32(acc, a, b);
  }
  size_t p = p0 + R + qr;
  int h0 = 2*ql, h1 = 2*ql+1;
  g_pb[(size_t)h0*LLc + p]     = acc[0];
  g_pb[(size_t)h1*LLc + p]     = acc[1];
  g_pb[(size_t)h0*LLc + p + 8] = acc[2];
  g_pb[(size_t)h1*LLc + p + 8] = acc[3];
}

// ---- K2: seq-weight logits + softmax over n ----------------------------------
__global__ __launch_bounds__(256) void k_swl(){
  __shared__ float sq[256]; __shared__ float sL[256][9];
  __shared__ float smx[8], srs[8];
  int i = blockIdx.x, t = threadIdx.x;
  sq[t] = g_qsw[i*HD+t];
  __syncthreads();
  const float* kr = g_ksw + ((size_t)t*Ll + i)*HD;
  float lg[8];
#pragma unroll
  for(int h=0;h<8;h++){
    float s=0.f;
#pragma unroll
    for(int f=0;f<8;f++){
      float4 kx = *(const float4*)(kr + h*32 + f*4);
      int c = h*32+f*4;
      s += kx.x*sq[c]+kx.y*sq[c+1]+kx.z*sq[c+2]+kx.w*sq[c+3];
    }
    lg[h]=s; sL[t][h]=s;
  }
  __syncthreads();
  { int w=t>>5, lane=t&31;
    float mx=-3.4e38f;
#pragma unroll
    for(int e=0;e<8;e++) mx=fmaxf(mx, sL[lane*8+e][w]);
    mx=warpMax(mx);
    float s=0.f;
#pragma unroll
    for(int e=0;e<8;e++) s+=expf(sL[lane*8+e][w]-mx);
    s=warpSum(s);
    if(lane==0){ smx[w]=mx; srs[w]=1.f/s; } }
  __syncthreads();
  size_t o = ((size_t)t*Ll + i)*Hh;
#pragma unroll
  for(int h=0;h<8;h++) g_sw[o+h] = expf(lg[h]-smx[h])*srs[h];
}

// ---- K_qs: Q * seqweight -> fp16 ---------------------------------------------
__global__ __launch_bounds__(256) void k_qs(){
  int u = blockIdx.x*256 + threadIdx.x;
  int row = u>>6, c4 = (u&63)*4;
  float sv = g_sw[(size_t)row*Hh + (c4>>5)];
  float4 x = *(const float4*)(g_mq + (size_t)row*HD + c4);
  uint2 o;
  o.x = pk2(x.x*sv, x.y*sv);
  o.y = pk2(x.z*sv, x.w*sv);
  *(uint2*)(g_qst + (size_t)row*HD + c4) = o;
}

// ---- K4: attn logits fp16, 128x64 tile, K-chunk 64 (2 n per stage) -----------
#define ATTN_SMEM (2*27648)
__global__ __launch_bounds__(256) void k_attn(){
  extern __shared__ char dsm[];
  const uint32_t sb = s2u(dsm);
  const int t = threadIdx.x, h = blockIdx.z, i0 = blockIdx.x*128, j0 = blockIdx.y*64;
  const int w = t>>5, lane = t&31;
  const int wm = w>>1, wn = w&1;
  const int qr = lane>>2, ql = lane&3;
  const uint32_t aLn = ((wm*32 + (lane&15))*72 + ((lane>>4)<<3))*2;
  const uint32_t bLn = ((wn*32 + (lane&7) + ((lane&16)>>1))*72 + (((lane>>3)&1)<<3))*2;
  float acc[2][4][4];
#pragma unroll
  for(int am=0;am<2;am++)
#pragma unroll
    for(int bn=0;bn<4;bn++)
#pragma unroll
      for(int e=0;e<4;e++) acc[am][bn][e]=0.f;

  // prefetch it=0 (n=0,1)
#pragma unroll
  for(int c=0;c<4;c++){ int u=c*256+t, r=u>>3, cu=u&7;
    int nsel = cu>>2, d0 = (cu&3)*8;
    cpa16(sb + r*144 + cu*16, g_qst + ((size_t)nsel*Ll + i0 + r)*HD + h*32 + d0); }
#pragma unroll
  for(int c=0;c<2;c++){ int u=c*256+t, r=u>>3, cu=u&7;
    int nsel = cu>>2, d0 = (cu&3)*8;
    cpa16(sb + 18432 + r*144 + cu*16, g_kt + ((size_t)nsel*Ll + j0 + r)*HD + h*32 + d0); }
  CPC();
  for(int it=0; it<128; it++){
    if(it+1<128){
      uint32_t dst = sb + ((it+1)&1)*27648;
      int nbase = 2*(it+1);
#pragma unroll
      for(int c=0;c<4;c++){ int u=c*256+t, r=u>>3, cu=u&7;
        int nsel = cu>>2, d0 = (cu&3)*8;
        cpa16(dst + r*144 + cu*16, g_qst + ((size_t)(nbase+nsel)*Ll + i0 + r)*HD + h*32 + d0); }
#pragma unroll
      for(int c=0;c<2;c++){ int u=c*256+t, r=u>>3, cu=u&7;
        int nsel = cu>>2, d0 = (cu&3)*8;
        cpa16(dst + 18432 + r*144 + cu*16, g_kt + ((size_t)(nbase+nsel)*Ll + j0 + r)*HD + h*32 + d0); }
      CPC(); CPW1();
    } else CPW0();
    __syncthreads();
    const uint32_t st = sb + (it&1)*27648;
    const uint32_t bst = st + 18432;
#pragma unroll
    for(int ks=0;ks<4;ks++){
      const uint32_t kb = ks*32;
      unsigned a0[4], a1[4], bf0[4], bf1[4];
      ldsm4(a0, st + aLn + kb);
      ldsm4(a1, st + aLn + 16*144 + kb);
      ldsm4(bf0, bst + bLn + kb);
      ldsm4(bf1, bst + bLn + 16*144 + kb);
      mma_f16(acc[0][0], a0, bf0);  mma_f16(acc[0][1], a0, bf0+2);
      mma_f16(acc[0][2], a0, bf1);  mma_f16(acc[0][3], a0, bf1+2);
      mma_f16(acc[1][0], a1, bf0);  mma_f16(acc[1][1], a1, bf0+2);
      mma_f16(acc[1][2], a1, bf1);  mma_f16(acc[1][3], a1, bf1+2);
    }
    __syncthreads();
  }
  const size_t hb = (size_t)h*LLc;
#pragma unroll
  for(int am=0;am<2;am++){
    int i = i0 + wm*32 + am*16 + qr;
#pragma unroll
    for(int bn=0;bn<4;bn++){
      int j = j0 + wn*32 + bn*8 + 2*ql;
      size_t o = hb + (size_t)i*Ll + j;
      float2 pb0 = *(const float2*)(g_pb+o);
      *(float2*)(g_attn+o) = make_float2(acc[am][bn][0]+pb0.x, acc[am][bn][1]+pb0.y);
      size_t o2 = o + (size_t)8*Ll;
      float2 pb1 = *(const float2*)(g_pb+o2);
      *(float2*)(g_attn+o2) = make_float2(acc[am][bn][2]+pb1.x, acc[am][bn][3]+pb1.y);
    }
  }
}

// ---- K5: softmax over j -> fp16 probs ----------------------------------------
__global__ void k_attnsoftmax(){
  int b = blockIdx.x, h = b/Ll, i = b%Ll, t = threadIdx.x;
  __shared__ float red[32];
  size_t base = (size_t)h*LLc + (size_t)i*Ll;
  float x0 = g_attn[base+t], x1 = g_attn[base+128+t], x2 = g_attn[base+256+t];
  float mx = blockMax(fmaxf(x0,fmaxf(x1,x2)), red, 4);
  float e0=expf(x0-mx), e1=expf(x1-mx), e2=expf(x2-mx);
  float s = blockSum(e0+e1+e2, red, 4);
  float inv = 1.f/s;
  g_pt[base+t]     = __float2half_rn(e0*inv);
  g_pt[base+128+t] = __float2half_rn(e1*inv);
  g_pt[base+256+t] = __float2half_rn(e2*inv);
}

// ---- K6: P @ V fp16, epilogue fuses gate, writes fp16 g_og -------------------
#define PV_SMEM (2*20480)
__global__ __launch_bounds__(256) void k_pv(){
  extern __shared__ char dsm[];
  const uint32_t sb = s2u(dsm);
  const int t = threadIdx.x, h = blockIdx.z, i0 = blockIdx.x*128, n0 = blockIdx.y*4;
  const int w = t>>5, lane = t&31;
  const int wm = w>>1, wn = w&1;
  const int qr = lane>>2, ql = lane&3;
  const uint32_t aLn = ((wm*32 + (lane&15))*40 + ((lane>>4)<<3))*2;
  const uint32_t bLn = ((wn*64 + (lane&7) + ((lane&16)>>1))*40 + (((lane>>3)&1)<<3))*2;
  float acc[2][8][4];
#pragma unroll
  for(int am=0;am<2;am++)
#pragma unroll
    for(int bn=0;bn<8;bn++)
#pragma unroll
      for(int e=0;e<4;e++) acc[am][bn][e]=0.f;

  const size_t aBase = (size_t)h*LLc + (size_t)i0*Ll;
#pragma unroll
  for(int c=0;c<2;c++){ int u=c*256+t, r=u>>2, cu=u&3;
    cpa16(sb + r*80 + cu*16, g_pt + aBase + (size_t)r*Ll + cu*8); }
#pragma unroll
  for(int c=0;c<2;c++){ int u=c*256+t, rr=u>>2, cu=u&3;
    size_t grow = ((size_t)(n0+(rr>>5))*8 + h)*32 + (rr&31);
    cpa16(sb + 10240 + rr*80 + cu*16, g_vT + grow*Ll + cu*8); }
  CPC();
  for(int jc=0;jc<12;jc++){
    if(jc+1<12){
      int j1 = (jc+1)*32;
      uint32_t dst = sb + ((jc+1)&1)*20480;
#pragma unroll
      for(int c=0;c<2;c++){ int u=c*256+t, r=u>>2, cu=u&3;
        cpa16(dst + r*80 + cu*16, g_pt + aBase + (size_t)r*Ll + j1 + cu*8); }
#pragma unroll
      for(int c=0;c<2;c++){ int u=c*256+t, rr=u>>2, cu=u&3;
        size_t grow = ((size_t)(n0+(rr>>5))*8 + h)*32 + (rr&31);
        cpa16(dst + 10240 + rr*80 + cu*16, g_vT + grow*Ll + j1 + cu*8); }
      CPC(); CPW1();
    } else CPW0();
    __syncthreads();
    const uint32_t st = sb + (jc&1)*20480;
    const uint32_t bst = st + 10240;
#pragma unroll
    for(int ks=0;ks<2;ks++){
      const uint32_t kb = ks*32;
      unsigned a0[4], a1[4], bf[4][4];
      ldsm4(a0, st + aLn + kb);
      ldsm4(a1, st + aLn + 16*80 + kb);
#pragma unroll
      for(int q=0;q<4;q++) ldsm4(bf[q], bst + bLn + q*16*80 + kb);
#pragma unroll
      for(int bn=0;bn<8;bn++){
        mma_f16(acc[0][bn], a0, bf[bn>>1] + 2*(bn&1));
        mma_f16(acc[1][bn], a1, bf[bn>>1] + 2*(bn&1));
      }
    }
    __syncthreads();
  }
#pragma unroll
  for(int am=0;am<2;am++){
    int i = i0 + wm*32 + am*16 + qr;
#pragma unroll
    for(int bn=0;bn<8;bn++){
      int col = wn*64 + bn*8 + 2*ql;
      int nv = col>>5, dd = col&31;
      size_t o = ((size_t)(n0+nv)*Ll + i)*HD + h*Dd + dd;
      float2 ga = *(const float2*)(g_gate+o);
      *(unsigned*)(g_og+o) = pk2(acc[am][bn][0]*ga.x, acc[am][bn][1]*ga.y);
      size_t o2 = o + (size_t)8*HD;
      float2 gb = *(const float2*)(g_gate+o2);
      *(unsigned*)(g_og+o2) = pk2(acc[am][bn][2]*gb.x, acc[am][bn][3]*gb.y);
    }
  }
}

// ---- K7: out projection fp16, CTA 128x128, warp 32x64, K-chunk 64 ------------
__global__ __launch_bounds__(256) void k_out(const float* __restrict__ bo,
                                             float* __restrict__ out){
  extern __shared__ char dsm[];
  const uint32_t sb = s2u(dsm);
  const int t = threadIdx.x;
  const size_t row0 = (size_t)blockIdx.y*128;
  const int nb = blockIdx.x*128;             // 0 or 128
  const __half* Bsrc = g_wt + ((size_t)5*256 + nb)*256;

  const int w = t>>5, lane = t&31;
  const int wm = w>>1, wn = w&1;
  const int qr = lane>>2, ql = lane&3;
  const uint32_t aLn = ((wm*32 + (lane&15))*72 + ((lane>>4)<<3))*2;
  const uint32_t bLn = ((wn*64 + (lane&7) + ((lane&16)>>1))*72 + (((lane>>3)&1)<<3))*2;

#pragma unroll
  for(int c=0;c<4;c++){ int u=c*256+t, r=u>>3, cu=u&7;
    cpa16(sb + r*144 + cu*16, g_og + (row0+r)*HD + cu*8); }
#pragma unroll
  for(int c=0;c<4;c++){ int u=c*256+t, r=u>>3, cu=u&7;
    cpa16(sb + 18432 + r*144 + cu*16, Bsrc + (size_t)r*256 + cu*8); }
  CPC();

  float acc[2][8][4];
#pragma unroll
  for(int am=0;am<2;am++)
#pragma unroll
    for(int bn=0;bn<8;bn++)
#pragma unroll
      for(int e=0;e<4;e++) acc[am][bn][e]=0.f;

  for(int kc=0;kc<4;kc++){
    if(kc+1<4){
      int k1 = (kc+1)*64;
      uint32_t dst = sb + ((kc+1)&1)*36864;
#pragma unroll
      for(int c=0;c<4;c++){ int u=c*256+t, r=u>>3, cu=u&7;
        cpa16(dst + r*144 + cu*16, g_og + (row0+r)*HD + k1 + cu*8); }
#pragma unroll
      for(int c=0;c<4;c++){ int u=c*256+t, r=u>>3, cu=u&7;
        cpa16(dst + 18432 + r*144 + cu*16, Bsrc + (size_t)r*256 + k1 + cu*8); }
      CPC(); CPW1();
    } else CPW0();
    __syncthreads();
    const uint32_t st = sb + (kc&1)*36864;
    const uint32_t bst = st + 18432;
#pragma unroll
    for(int ks=0;ks<4;ks++){
      const uint32_t kb = ks*32;
      unsigned a0[4], a1[4], bf[4][4];
      ldsm4(a0, st + aLn + kb);
      ldsm4(a1, st + aLn + 16*144 + kb);
#pragma unroll
      for(int q=0;q<4;q++) ldsm4(bf[q], bst + bLn + q*16*144 + kb);
#pragma unroll
      for(int bn=0;bn<8;bn++){
        mma_f16(acc[0][bn], a0, bf[bn>>1] + 2*(bn&1));
        mma_f16(acc[1][bn], a1, bf[bn>>1] + 2*(bn&1));
      }
    }
    __syncthreads();
  }
#pragma unroll
  for(int am=0;am<2;am++){
    int rowa = (int)row0 + wm*32 + am*16 + qr;
#pragma unroll
    for(int bn=0;bn<8;bn++){
      int cg = nb + wn*64 + bn*8 + 2*ql;
      float2 b2 = *(const float2*)(bo + cg);
      *(float2*)(out + (size_t)rowa*HD + cg) = make_float2(acc[am][bn][0]+b2.x, acc[am][bn][1]+b2.y);
      *(float2*)(out + (size_t)(rowa+8)*HD + cg) = make_float2(acc[am][bn][2]+b2.x, acc[am][bn][3]+b2.y);
    }
  }
}

// ---- launch ------------------------------------------------------------------
extern "C" void kernel_launch(void* const* d_in, const int* in_sizes, int n_in,
                              void* d_out, int out_size){
  const float* msa      = (const float*)d_in[0];
  const float* pair     = (const float*)d_in[1];
  const float* ln_msa_g = (const float*)d_in[2];
  const float* ln_msa_b = (const float*)d_in[3];
  const float* ln_pair_g= (const float*)d_in[4];
  const float* ln_pair_b= (const float*)d_in[5];
  const float* sw_wq    = (const float*)d_in[6];
  const float* sw_bq    = (const float*)d_in[7];
  const float* sw_wk    = (const float*)d_in[8];
  const float* sw_bk    = (const float*)d_in[9];
  const float* wq       = (const float*)d_in[10];
  const float* wk       = (const float*)d_in[11];
  const float* wv       = (const float*)d_in[12];
  const float* wb       = (const float*)d_in[13];
  const float* wg       = (const float*)d_in[14];
  const float* bg       = (const float*)d_in[15];
  const float* wo       = (const float*)d_in[16];
  const float* bo       = (const float*)d_in[17];
  float* out = (float*)d_out;

  cudaFuncSetAttribute(k_proj, cudaFuncAttributeMaxDynamicSharedMemorySize, PROJ_SMEM);
  cudaFuncSetAttribute(k_attn, cudaFuncAttributeMaxDynamicSharedMemorySize, ATTN_SMEM);
  cudaFuncSetAttribute(k_pv,   cudaFuncAttributeMaxDynamicSharedMemorySize, PV_SMEM);
  cudaFuncSetAttribute(k_out,  cudaFuncAttributeMaxDynamicSharedMemorySize, PROJ_SMEM);
  cudaFuncSetAttribute(k_pbmm, cudaFuncAttributeMaxDynamicSharedMemorySize, PB_SMEM);

  k_prep<<<6*256, 256>>>(sw_wk, wq, wk, wv, wg, wo);          // 1
  k_qsw<<<Ll, 256>>>(msa, ln_msa_g, ln_msa_b, sw_wq, sw_bq);  // 2
  k_ln<<<NL/32, 256>>>(msa, ln_msa_g, ln_msa_b);              // 3
  k_proj<<<dim3(10, NL/128), 256, PROJ_SMEM>>>(sw_bk, bg);    // 4 (ncu slot)
  k_pbmm<<<LLc/128, 256, PB_SMEM>>>(pair, ln_pair_g, ln_pair_b, wb); // 5
  k_swl<<<Ll, 256>>>();                                       // 6
  k_qs<<<NL*HD/1024, 256>>>();                                // 7
  k_attn<<<dim3(3,6,8), 256, ATTN_SMEM>>>();                  // 8
  k_attnsoftmax<<<Hh*Ll, 128>>>();                            // 9
  k_pv<<<dim3(3,64,8), 256, PV_SMEM>>>();                     // 10
  k_out<<<dim3(2, NL/128), 256, PROJ_SMEM>>>(bo, out);        // 11
}

// round 17
// speedup vs baseline: 1.5600x; 1.0552x over previous
#include <cuda_runtime.h>
#include <cuda_fp16.h>
#include <math.h>
#include <stdint.h>

#define Nn 256
#define Ll 384
#define Hh 8
#define Dd 32
#define HD 256
#define NL (Nn*Ll)
#define LLc (Ll*Ll)
#define ISD 0.17677669529663687f

// fp32 scratch
__device__ float g_qsw[Ll*HD];
__device__ float g_sw[NL*Hh];
__device__ float g_pb[Hh*LLc];
__device__ float g_attn[Hh*LLc];
// fp16 operands / intermediates
__device__ __half g_at[NL*HD];
__device__ __half g_wt[6*256*256];
__device__ __half g_ksw[NL*HD];
__device__ __half g_mq[NL*HD];
__device__ __half g_gate[NL*HD];
__device__ __half g_kt[NL*HD];
__device__ __half g_qst[NL*HD];
__device__ __half g_pt[Hh*LLc];
__device__ __half g_vT[NL*HD];
__device__ __half g_og[NL*HD];

// ---------------- helpers ----------------------------------------------------
__device__ __forceinline__ unsigned f2tf(float x){
  unsigned u; asm("cvt.rna.tf32.f32 %0, %1;" : "=r"(u) : "f"(x)); return u;
}
__device__ __forceinline__ unsigned pk2(float x, float y){
  __half2 h = __floats2half2_rn(x, y);
  return *(unsigned*)&h;
}
__device__ __forceinline__ void mma_f16(float c[4], const unsigned a[4], const unsigned b[2]){
  asm volatile("mma.sync.aligned.m16n8k16.row.col.f32.f16.f16.f32 "
    "{%0,%1,%2,%3},{%4,%5,%6,%7},{%8,%9},{%0,%1,%2,%3};"
    : "+f"(c[0]),"+f"(c[1]),"+f"(c[2]),"+f"(c[3])
    : "r"(a[0]),"r"(a[1]),"r"(a[2]),"r"(a[3]),"r"(b[0]),"r"(b[1]));
}
__device__ __forceinline__ void mma_tf32(float c[4], const unsigned a[4], const unsigned b[2]){
  asm volatile("mma.sync.aligned.m16n8k8.row.col.f32.tf32.tf32.f32 "
    "{%0,%1,%2,%3},{%4,%5,%6,%7},{%8,%9},{%0,%1,%2,%3};"
    : "+f"(c[0]),"+f"(c[1]),"+f"(c[2]),"+f"(c[3])
    : "r"(a[0]),"r"(a[1]),"r"(a[2]),"r"(a[3]),"r"(b[0]),"r"(b[1]));
}
__device__ __forceinline__ void ldsm4(unsigned r[4], uint32_t a){
  asm volatile("ldmatrix.sync.aligned.m8n8.x4.shared.b16 {%0,%1,%2,%3}, [%4];"
    : "=r"(r[0]),"=r"(r[1]),"=r"(r[2]),"=r"(r[3]) : "r"(a));
}
__device__ __forceinline__ uint32_t s2u(const void* p){
  uint32_t a; asm("{ .reg .u64 t; cvta.to.shared.u64 t, %1; cvt.u32.u64 %0, t; }" : "=r"(a) : "l"(p)); return a;
}
__device__ __forceinline__ void cpa16(uint32_t s, const void* g){
  asm volatile("cp.async.cg.shared.global [%0], [%1], 16;" :: "r"(s), "l"(g));
}
#define CPC() asm volatile("cp.async.commit_group;" ::: "memory")
#define CPW1() asm volatile("cp.async.wait_group 1;" ::: "memory")
#define CPW0() asm volatile("cp.async.wait_group 0;" ::: "memory")

__device__ __forceinline__ float warpSum(float v){
#pragma unroll
  for(int o=16;o;o>>=1) v += __shfl_xor_sync(0xffffffffu, v, o);
  return v;
}
__device__ __forceinline__ float warpMax(float v){
#pragma unroll
  for(int o=16;o;o>>=1) v = fmaxf(v, __shfl_xor_sync(0xffffffffu, v, o));
  return v;
}
__device__ __forceinline__ float blockSum(float v, float* red, int nw){
  int t=threadIdx.x; v=warpSum(v);
  if((t&31)==0) red[t>>5]=v;
  __syncthreads();
  float s=0.f;
  if(t<32){ s=(t<nw)?red[t]:0.f; s=warpSum(s); if(t==0) red[0]=s; }
  __syncthreads(); s=red[0]; __syncthreads(); return s;
}
__device__ __forceinline__ float blockMax(float v, float* red, int nw){
  int t=threadIdx.x; v=warpMax(v);
  if((t&31)==0) red[t>>5]=v;
  __syncthreads();
  float s=-3.4e38f;
  if(t<32){ s=(t<nw)?red[t]:-3.4e38f; s=warpMax(s); if(t==0) red[0]=s; }
  __syncthreads(); s=red[0]; __syncthreads(); return s;
}

// ---- prep: convert+transpose 6 weight mats to fp16 [mat][n][k] ---------------
__global__ void k_prep(const float* __restrict__ w0, const float* __restrict__ w1,
                       const float* __restrict__ w2, const float* __restrict__ w3,
                       const float* __restrict__ w4, const float* __restrict__ w5){
  int bid = blockIdx.x, t = threadIdx.x;
  int mat = bid>>8, n = bid&255;
  const float* W = (mat==0)?w0:(mat==1)?w1:(mat==2)?w2:(mat==3)?w3:(mat==4)?w4:w5;
  g_wt[(size_t)bid*256 + t] = __float2half_rn(W[t*256 + n]);
}

// ---- K_ln: LN(msa) -> fp16 g_at ----------------------------------------------
__global__ __launch_bounds__(256) void k_ln(const float* __restrict__ msa,
    const float* __restrict__ lng, const float* __restrict__ lnb){
  size_t r = (size_t)blockIdx.x*32 + (threadIdx.x>>3);
  int q = threadIdx.x&7;
  const float* rp = msa + r*HD + q*32;
  float4 xv[8];
  float s=0.f, ss=0.f;
#pragma unroll
  for(int f=0;f<8;f++){
    xv[f] = *(const float4*)(rp + f*4);
    s  += xv[f].x+xv[f].y+xv[f].z+xv[f].w;
    ss += xv[f].x*xv[f].x+xv[f].y*xv[f].y+xv[f].z*xv[f].z+xv[f].w*xv[f].w;
  }
#pragma unroll
  for(int o=1;o<8;o<<=1){ s += __shfl_xor_sync(0xffffffffu,s,o); ss += __shfl_xor_sync(0xffffffffu,ss,o); }
  float mean = s*(1.f/HD), inv = rsqrtf(ss*(1.f/HD)-mean*mean+1e-5f);
#pragma unroll
  for(int f=0;f<8;f++){
    int c = q*32 + f*4;
    uint2 o;
    o.x = pk2((xv[f].x-mean)*inv*lng[c  ]+lnb[c  ], (xv[f].y-mean)*inv*lng[c+1]+lnb[c+1]);
    o.y = pk2((xv[f].z-mean)*inv*lng[c+2]+lnb[c+2], (xv[f].w-mean)*inv*lng[c+3]+lnb[c+3]);
    *(uint2*)(g_at + r*HD + c) = o;
  }
}

// ---- K0: qsw row 0 -----------------------------------------------------------
__global__ void k_qsw(const float* __restrict__ msa, const float* __restrict__ lng,
                      const float* __restrict__ lnb, const float* __restrict__ swq,
                      const float* __restrict__ sbq){
  int i = blockIdx.x, t = threadIdx.x;
  __shared__ float sm[HD]; __shared__ float red[32];
  float x = msa[(size_t)i*HD + t];
  float mean = blockSum(x, red, 8)*(1.f/HD);
  float d = x-mean;
  float var = blockSum(d*d, red, 8)*(1.f/HD);
  sm[t] = d*rsqrtf(var+1e-5f)*lng[t]+lnb[t];
  __syncthreads();
  float acc = sbq[t];
#pragma unroll 8
  for(int r=0;r<HD;r++) acc += sm[r]*swq[r*HD+t];
  g_qsw[i*HD+t] = acc*ISD;
}

// ---- K1: 5 projections fp16, CTA 128x128, warp 32x64, K-chunk 64 -------------
#define PROJ_SMEM (2*36864)
__global__ __launch_bounds__(256) void k_proj(const float* __restrict__ sbk,
                                              const float* __restrict__ bg){
  extern __shared__ char dsm[];
  const uint32_t sb = s2u(dsm);
  const int t = threadIdx.x;
  const size_t row0 = (size_t)blockIdx.y*128;
  const int by = blockIdx.x;                 // 0..9
  const int mi = by>>1, nb = (by&1)*128;
  const int nn = (int)(row0/Ll);
  const int ibase = (int)(row0%Ll);
  const __half* Bsrc = g_wt + ((size_t)mi*256 + nb)*256;

  const int w = t>>5, lane = t&31;
  const int wm = w>>1, wn = w&1;
  const int qr = lane>>2, ql = lane&3;
  const uint32_t aLn = ((wm*32 + (lane&15))*72 + ((lane>>4)<<3))*2;
  const uint32_t bLn = ((wn*64 + (lane&7) + ((lane&16)>>1))*72 + (((lane>>3)&1)<<3))*2;

#pragma unroll
  for(int c=0;c<4;c++){ int u=c*256+t, r=u>>3, cu=u&7;
    cpa16(sb + r*144 + cu*16, g_at + (row0+r)*HD + cu*8); }
#pragma unroll
  for(int c=0;c<4;c++){ int u=c*256+t, r=u>>3, cu=u&7;
    cpa16(sb + 18432 + r*144 + cu*16, Bsrc + (size_t)r*256 + cu*8); }
  CPC();

  float acc[2][8][4];
#pragma unroll
  for(int am=0;am<2;am++)
#pragma unroll
    for(int bn=0;bn<8;bn++)
#pragma unroll
      for(int e=0;e<4;e++) acc[am][bn][e]=0.f;

  for(int kc=0;kc<4;kc++){
    if(kc+1<4){
      int k1 = (kc+1)*64;
      uint32_t dst = sb + ((kc+1)&1)*36864;
#pragma unroll
      for(int c=0;c<4;c++){ int u=c*256+t, r=u>>3, cu=u&7;
        cpa16(dst + r*144 + cu*16, g_at + (row0+r)*HD + k1 + cu*8); }
#pragma unroll
      for(int c=0;c<4;c++){ int u=c*256+t, r=u>>3, cu=u&7;
        cpa16(dst + 18432 + r*144 + cu*16, Bsrc + (size_t)r*256 + k1 + cu*8); }
      CPC(); CPW1();
    } else CPW0();
    __syncthreads();
    const uint32_t st = sb + (kc&1)*36864;
    const uint32_t bst = st + 18432;
#pragma unroll
    for(int ks=0;ks<4;ks++){
      const uint32_t kb = ks*32;
      unsigned a0[4], a1[4], bf[4][4];
      ldsm4(a0, st + aLn + kb);
      ldsm4(a1, st + aLn + 16*144 + kb);
#pragma unroll
      for(int q=0;q<4;q++) ldsm4(bf[q], bst + bLn + q*16*144 + kb);
#pragma unroll
      for(int bn=0;bn<8;bn++){
        mma_f16(acc[0][bn], a0, bf[bn>>1] + 2*(bn&1));
        mma_f16(acc[1][bn], a1, bf[bn>>1] + 2*(bn&1));
      }
    }
    __syncthreads();
  }
#pragma unroll
  for(int am=0;am<2;am++){
    int rloc = wm*32 + am*16 + qr;
    int rowa = (int)row0 + rloc;
#pragma unroll
    for(int bn=0;bn<8;bn++){
      int cg = nb + wn*64 + bn*8 + 2*ql;
      size_t o0 = (size_t)rowa*HD + cg, o1 = o0 + 8*HD;
      float v0=acc[am][bn][0], v1=acc[am][bn][1], v2=acc[am][bn][2], v3=acc[am][bn][3];
      if(mi==0){
        float b0=sbk[cg], b1=sbk[cg+1];
        *(unsigned*)(g_ksw+o0) = pk2(v0+b0, v1+b1);
        *(unsigned*)(g_ksw+o1) = pk2(v2+b0, v3+b1);
      } else if(mi==1){
        *(unsigned*)(g_mq+o0) = pk2(v0, v1);
        *(unsigned*)(g_mq+o1) = pk2(v2, v3);
      } else if(mi==2){
        *(unsigned*)(g_kt+o0) = pk2(v0*ISD, v1*ISD);
        *(unsigned*)(g_kt+o1) = pk2(v2*ISD, v3*ISD);
      } else if(mi==3){
        int i = ibase + rloc;
        size_t d0 = ((size_t)(nn*8 + (cg>>5))*32 + (cg&31))*Ll + i;
        g_vT[d0]      = __float2half_rn(v0);
        g_vT[d0+Ll]   = __float2half_rn(v1);
        g_vT[d0+8]    = __float2half_rn(v2);
        g_vT[d0+Ll+8] = __float2half_rn(v3);
      } else {
        float b0=bg[cg], b1=bg[cg+1];
        *(unsigned*)(g_gate+o0) = pk2(1.f/(1.f+expf(-(v0+b0))), 1.f/(1.f+expf(-(v1+b1))));
        *(unsigned*)(g_gate+o1) = pk2(1.f/(1.f+expf(-(v2+b0))), 1.f/(1.f+expf(-(v3+b1))));
      }
    }
  }
}

// ---- K3: pair LN + bias projection via tf32 MMA ------------------------------
#define PB_SMEM ((128*132 + 1024)*4)
__global__ __launch_bounds__(256) void k_pbmm(const float* __restrict__ pair,
    const float* __restrict__ lnpg, const float* __restrict__ lnpb,
    const float* __restrict__ wb){
  extern __shared__ char dsmc[];
  unsigned* dsm = (unsigned*)dsmc;
  unsigned (*sA)[132] = (unsigned(*)[132])dsm;
  unsigned* swb = dsm + 128*132;
  const uint32_t sbA = s2u(dsm);
  const int t = threadIdx.x;
  const size_t p0 = (size_t)blockIdx.x*128;
  for(int u=t; u<1024; u+=256) swb[u] = f2tf(wb[u]);
  {
    int row = t>>1, half = t&1;
    const float* rp = pair + (p0+row)*128 + half*64;
    float s=0.f, ss=0.f;
#pragma unroll
    for(int f=0;f<16;f++){ float4 x = *(const float4*)(rp+f*4);
      s += x.x+x.y+x.z+x.w; ss += x.x*x.x+x.y*x.y+x.z*x.z+x.w*x.w; }
    s  += __shfl_xor_sync(0xffffffffu, s, 1);
    ss += __shfl_xor_sync(0xffffffffu, ss, 1);
    float mean = s*(1.f/128.f), inv = rsqrtf(ss*(1.f/128.f)-mean*mean+1e-5f);
#pragma unroll
    for(int f=0;f<16;f++){
      int c = half*64 + f*4;
      float4 x = *(const float4*)(pair + (p0+row)*128 + c);
      sA[row][c  ] = f2tf((x.x-mean)*inv*lnpg[c  ]+lnpb[c  ]);
      sA[row][c+1] = f2tf((x.y-mean)*inv*lnpg[c+1]+lnpb[c+1]);
      sA[row][c+2] = f2tf((x.z-mean)*inv*lnpg[c+2]+lnpb[c+2]);
      sA[row][c+3] = f2tf((x.w-mean)*inv*lnpg[c+3]+lnpb[c+3]);
    }
  }
  __syncthreads();
  const int w = t>>5, lane = t&31;
  const int qr = lane>>2, ql = lane&3;
  const int R = w*16;
  const uint32_t aoff = sbA + ((R + (lane&15))*132 + ((lane>>4)<<2))*4;
  float acc[4] = {0.f,0.f,0.f,0.f};
#pragma unroll
  for(int ks=0; ks<16; ks++){
    unsigned a[4], b[2];
    ldsm4(a, aoff + ks*32);
    b[0] = swb[(ks*8+ql  )*8 + qr];
    b[1] = swb[(ks*8+ql+4)*8 + qr];
    mma_tf32(acc, a, b);
  }
  size_t p = p0 + R + qr;
  int h0 = 2*ql, h1 = 2*ql+1;
  g_pb[(size_t)h0*LLc + p]     = acc[0];
  g_pb[(size_t)h1*LLc + p]     = acc[1];
  g_pb[(size_t)h0*LLc + p + 8] = acc[2];
  g_pb[(size_t)h1*LLc + p + 8] = acc[3];
}

// ---- K2: seq-weight logits + softmax over n (reads fp16 K) -------------------
__global__ __launch_bounds__(256) void k_swl(){
  __shared__ float sq[256]; __shared__ float sL[256][9];
  __shared__ float smx[8], srs[8];
  int i = blockIdx.x, t = threadIdx.x;
  sq[t] = g_qsw[i*HD+t];
  __syncthreads();
  const __half* kr = g_ksw + ((size_t)t*Ll + i)*HD;
  float lg[8];
#pragma unroll
  for(int h=0;h<8;h++){
    float s=0.f;
#pragma unroll
    for(int f=0;f<4;f++){
      uint4 kx4 = *(const uint4*)(kr + h*32 + f*8);
      const __half2* hp = (const __half2*)&kx4;
#pragma unroll
      for(int e=0;e<4;e++){
        float2 kv = __half22float2(hp[e]);
        int c = h*32 + f*8 + e*2;
        s += kv.x*sq[c] + kv.y*sq[c+1];
      }
    }
    lg[h]=s; sL[t][h]=s;
  }
  __syncthreads();
  { int w=t>>5, lane=t&31;
    float mx=-3.4e38f;
#pragma unroll
    for(int e=0;e<8;e++) mx=fmaxf(mx, sL[lane*8+e][w]);
    mx=warpMax(mx);
    float s=0.f;
#pragma unroll
    for(int e=0;e<8;e++) s+=expf(sL[lane*8+e][w]-mx);
    s=warpSum(s);
    if(lane==0){ smx[w]=mx; srs[w]=1.f/s; } }
  __syncthreads();
  size_t o = ((size_t)t*Ll + i)*Hh;
#pragma unroll
  for(int h=0;h<8;h++) g_sw[o+h] = expf(lg[h]-smx[h])*srs[h];
}

// ---- K_qs: Q * seqweight -> fp16 (reads fp16 mq) -----------------------------
__global__ __launch_bounds__(256) void k_qs(){
  int u = blockIdx.x*256 + threadIdx.x;
  int row = u>>6, c4 = (u&63)*4;
  float sv = g_sw[(size_t)row*Hh + (c4>>5)];
  uint2 x2 = *(const uint2*)(g_mq + (size_t)row*HD + c4);
  const __half2* hp = (const __half2*)&x2;
  float2 a = __half22float2(hp[0]), b = __half22float2(hp[1]);
  uint2 o;
  o.x = pk2(a.x*sv, a.y*sv);
  o.y = pk2(b.x*sv, b.y*sv);
  *(uint2*)(g_qst + (size_t)row*HD + c4) = o;
}

// ---- K4: attn logits fp16, 128x64 tile, K-chunk 64 (2 n per stage) -----------
#define ATTN_SMEM (2*27648)
__global__ __launch_bounds__(256) void k_attn(){
  extern __shared__ char dsm[];
  const uint32_t sb = s2u(dsm);
  const int t = threadIdx.x, h = blockIdx.z, i0 = blockIdx.x*128, j0 = blockIdx.y*64;
  const int w = t>>5, lane = t&31;
  const int wm = w>>1, wn = w&1;
  const int qr = lane>>2, ql = lane&3;
  const uint32_t aLn = ((wm*32 + (lane&15))*72 + ((lane>>4)<<3))*2;
  const uint32_t bLn = ((wn*32 + (lane&7) + ((lane&16)>>1))*72 + (((lane>>3)&1)<<3))*2;
  float acc[2][4][4];
#pragma unroll
  for(int am=0;am<2;am++)
#pragma unroll
    for(int bn=0;bn<4;bn++)
#pragma unroll
      for(int e=0;e<4;e++) acc[am][bn][e]=0.f;

#pragma unroll
  for(int c=0;c<4;c++){ int u=c*256+t, r=u>>3, cu=u&7;
    int nsel = cu>>2, d0 = (cu&3)*8;
    cpa16(sb + r*144 + cu*16, g_qst + ((size_t)nsel*Ll + i0 + r)*HD + h*32 + d0); }
#pragma unroll
  for(int c=0;c<2;c++){ int u=c*256+t, r=u>>3, cu=u&7;
    int nsel = cu>>2, d0 = (cu&3)*8;
    cpa16(sb + 18432 + r*144 + cu*16, g_kt + ((size_t)nsel*Ll + j0 + r)*HD + h*32 + d0); }
  CPC();
  for(int it=0; it<128; it++){
    if(it+1<128){
      uint32_t dst = sb + ((it+1)&1)*27648;
      int nbase = 2*(it+1);
#pragma unroll
      for(int c=0;c<4;c++){ int u=c*256+t, r=u>>3, cu=u&7;
        int nsel = cu>>2, d0 = (cu&3)*8;
        cpa16(dst + r*144 + cu*16, g_qst + ((size_t)(nbase+nsel)*Ll + i0 + r)*HD + h*32 + d0); }
#pragma unroll
      for(int c=0;c<2;c++){ int u=c*256+t, r=u>>3, cu=u&7;
        int nsel = cu>>2, d0 = (cu&3)*8;
        cpa16(dst + 18432 + r*144 + cu*16, g_kt + ((size_t)(nbase+nsel)*Ll + j0 + r)*HD + h*32 + d0); }
      CPC(); CPW1();
    } else CPW0();
    __syncthreads();
    const uint32_t st = sb + (it&1)*27648;
    const uint32_t bst = st + 18432;
#pragma unroll
    for(int ks=0;ks<4;ks++){
      const uint32_t kb = ks*32;
      unsigned a0[4], a1[4], bf0[4], bf1[4];
      ldsm4(a0, st + aLn + kb);
      ldsm4(a1, st + aLn + 16*144 + kb);
      ldsm4(bf0, bst + bLn + kb);
      ldsm4(bf1, bst + bLn + 16*144 + kb);
      mma_f16(acc[0][0], a0, bf0);  mma_f16(acc[0][1], a0, bf0+2);
      mma_f16(acc[0][2], a0, bf1);  mma_f16(acc[0][3], a0, bf1+2);
      mma_f16(acc[1][0], a1, bf0);  mma_f16(acc[1][1], a1, bf0+2);
      mma_f16(acc[1][2], a1, bf1);  mma_f16(acc[1][3], a1, bf1+2);
    }
    __syncthreads();
  }
  const size_t hb = (size_t)h*LLc;
#pragma unroll
  for(int am=0;am<2;am++){
    int i = i0 + wm*32 + am*16 + qr;
#pragma unroll
    for(int bn=0;bn<4;bn++){
      int j = j0 + wn*32 + bn*8 + 2*ql;
      size_t o = hb + (size_t)i*Ll + j;
      float2 pb0 = *(const float2*)(g_pb+o);
      *(float2*)(g_attn+o) = make_float2(acc[am][bn][0]+pb0.x, acc[am][bn][1]+pb0.y);
      size_t o2 = o + (size_t)8*Ll;
      float2 pb1 = *(const float2*)(g_pb+o2);
      *(float2*)(g_attn+o2) = make_float2(acc[am][bn][2]+pb1.x, acc[am][bn][3]+pb1.y);
    }
  }
}

// ---- K5: softmax over j -> fp16 probs ----------------------------------------
__global__ void k_attnsoftmax(){
  int b = blockIdx.x, h = b/Ll, i = b%Ll, t = threadIdx.x;
  __shared__ float red[32];
  size_t base = (size_t)h*LLc + (size_t)i*Ll;
  float x0 = g_attn[base+t], x1 = g_attn[base+128+t], x2 = g_attn[base+256+t];
  float mx = blockMax(fmaxf(x0,fmaxf(x1,x2)), red, 4);
  float e0=expf(x0-mx), e1=expf(x1-mx), e2=expf(x2-mx);
  float s = blockSum(e0+e1+e2, red, 4);
  float inv = 1.f/s;
  g_pt[base+t]     = __float2half_rn(e0*inv);
  g_pt[base+128+t] = __float2half_rn(e1*inv);
  g_pt[base+256+t] = __float2half_rn(e2*inv);
}

// ---- K6: P @ V fp16, epilogue fuses fp16 gate, writes fp16 g_og --------------
#define PV_SMEM (2*20480)
__global__ __launch_bounds__(256) void k_pv(){
  extern __shared__ char dsm[];
  const uint32_t sb = s2u(dsm);
  const int t = threadIdx.x, h = blockIdx.z, i0 = blockIdx.x*128, n0 = blockIdx.y*4;
  const int w = t>>5, lane = t&31;
  const int wm = w>>1, wn = w&1;
  const int qr = lane>>2, ql = lane&3;
  const uint32_t aLn = ((wm*32 + (lane&15))*40 + ((lane>>4)<<3))*2;
  const uint32_t bLn = ((wn*64 + (lane&7) + ((lane&16)>>1))*40 + (((lane>>3)&1)<<3))*2;
  float acc[2][8][4];
#pragma unroll
  for(int am=0;am<2;am++)
#pragma unroll
    for(int bn=0;bn<8;bn++)
#pragma unroll
      for(int e=0;e<4;e++) acc[am][bn][e]=0.f;

  const size_t aBase = (size_t)h*LLc + (size_t)i0*Ll;
#pragma unroll
  for(int c=0;c<2;c++){ int u=c*256+t, r=u>>2, cu=u&3;
    cpa16(sb + r*80 + cu*16, g_pt + aBase + (size_t)r*Ll + cu*8); }
#pragma unroll
  for(int c=0;c<2;c++){ int u=c*256+t, rr=u>>2, cu=u&3;
    size_t grow = ((size_t)(n0+(rr>>5))*8 + h)*32 + (rr&31);
    cpa16(sb + 10240 + rr*80 + cu*16, g_vT + grow*Ll + cu*8); }
  CPC();
  for(int jc=0;jc<12;jc++){
    if(jc+1<12){
      int j1 = (jc+1)*32;
      uint32_t dst = sb + ((jc+1)&1)*20480;
#pragma unroll
      for(int c=0;c<2;c++){ int u=c*256+t, r=u>>2, cu=u&3;
        cpa16(dst + r*80 + cu*16, g_pt + aBase + (size_t)r*Ll + j1 + cu*8); }
#pragma unroll
      for(int c=0;c<2;c++){ int u=c*256+t, rr=u>>2, cu=u&3;
        size_t grow = ((size_t)(n0+(rr>>5))*8 + h)*32 + (rr&31);
        cpa16(dst + 10240 + rr*80 + cu*16, g_vT + grow*Ll + j1 + cu*8); }
      CPC(); CPW1();
    } else CPW0();
    __syncthreads();
    const uint32_t st = sb + (jc&1)*20480;
    const uint32_t bst = st + 10240;
#pragma unroll
    for(int ks=0;ks<2;ks++){
      const uint32_t kb = ks*32;
      unsigned a0[4], a1[4], bf[4][4];
      ldsm4(a0, st + aLn + kb);
      ldsm4(a1, st + aLn + 16*80 + kb);
#pragma unroll
      for(int q=0;q<4;q++) ldsm4(bf[q], bst + bLn + q*16*80 + kb);
#pragma unroll
      for(int bn=0;bn<8;bn++){
        mma_f16(acc[0][bn], a0, bf[bn>>1] + 2*(bn&1));
        mma_f16(acc[1][bn], a1, bf[bn>>1] + 2*(bn&1));
      }
    }
    __syncthreads();
  }
#pragma unroll
  for(int am=0;am<2;am++){
    int i = i0 + wm*32 + am*16 + qr;
#pragma unroll
    for(int bn=0;bn<8;bn++){
      int col = wn*64 + bn*8 + 2*ql;
      int nv = col>>5, dd = col&31;
      size_t o = ((size_t)(n0+nv)*Ll + i)*HD + h*Dd + dd;
      float2 ga = __half22float2(*(const __half2*)(g_gate+o));
      *(unsigned*)(g_og+o) = pk2(acc[am][bn][0]*ga.x, acc[am][bn][1]*ga.y);
      size_t o2 = o + (size_t)8*HD;
      float2 gb = __half22float2(*(const __half2*)(g_gate+o2));
      *(unsigned*)(g_og+o2) = pk2(acc[am][bn][2]*gb.x, acc[am][bn][3]*gb.y);
    }
  }
}

// ---- K7: out projection fp16, CTA 128x128, warp 32x64, K-chunk 64 ------------
__global__ __launch_bounds__(256) void k_out(const float* __restrict__ bo,
                                             float* __restrict__ out){
  extern __shared__ char dsm[];
  const uint32_t sb = s2u(dsm);
  const int t = threadIdx.x;
  const size_t row0 = (size_t)blockIdx.y*128;
  const int nb = blockIdx.x*128;             // 0 or 128
  const __half* Bsrc = g_wt + ((size_t)5*256 + nb)*256;

  const int w = t>>5, lane = t&31;
  const int wm = w>>1, wn = w&1;
  const int qr = lane>>2, ql = lane&3;
  const uint32_t aLn = ((wm*32 + (lane&15))*72 + ((lane>>4)<<3))*2;
  const uint32_t bLn = ((wn*64 + (lane&7) + ((lane&16)>>1))*72 + (((lane>>3)&1)<<3))*2;

#pragma unroll
  for(int c=0;c<4;c++){ int u=c*256+t, r=u>>3, cu=u&7;
    cpa16(sb + r*144 + cu*16, g_og + (row0+r)*HD + cu*8); }
#pragma unroll
  for(int c=0;c<4;c++){ int u=c*256+t, r=u>>3, cu=u&7;
    cpa16(sb + 18432 + r*144 + cu*16, Bsrc + (size_t)r*256 + cu*8); }
  CPC();

  float acc[2][8][4];
#pragma unroll
  for(int am=0;am<2;am++)
#pragma unroll
    for(int bn=0;bn<8;bn++)
#pragma unroll
      for(int e=0;e<4;e++) acc[am][bn][e]=0.f;

  for(int kc=0;kc<4;kc++){
    if(kc+1<4){
      int k1 = (kc+1)*64;
      uint32_t dst = sb + ((kc+1)&1)*36864;
#pragma unroll
      for(int c=0;c<4;c++){ int u=c*256+t, r=u>>3, cu=u&7;
        cpa16(dst + r*144 + cu*16, g_og + (row0+r)*HD + k1 + cu*8); }
#pragma unroll
      for(int c=0;c<4;c++){ int u=c*256+t, r=u>>3, cu=u&7;
        cpa16(dst + 18432 + r*144 + cu*16, Bsrc + (size_t)r*256 + k1 + cu*8); }
      CPC(); CPW1();
    } else CPW0();
    __syncthreads();
    const uint32_t st = sb + (kc&1)*36864;
    const uint32_t bst = st + 18432;
#pragma unroll
    for(int ks=0;ks<4;ks++){
      const uint32_t kb = ks*32;
      unsigned a0[4], a1[4], bf[4][4];
      ldsm4(a0, st + aLn + kb);
      ldsm4(a1, st + aLn + 16*144 + kb);
#pragma unroll
      for(int q=0;q<4;q++) ldsm4(bf[q], bst + bLn + q*16*144 + kb);
#pragma unroll
      for(int bn=0;bn<8;bn++){
        mma_f16(acc[0][bn], a0, bf[bn>>1] + 2*(bn&1));
        mma_f16(acc[1][bn], a1, bf[bn>>1] + 2*(bn&1));
      }
    }
    __syncthreads();
  }
#pragma unroll
  for(int am=0;am<2;am++){
    int rowa = (int)row0 + wm*32 + am*16 + qr;
#pragma unroll
    for(int bn=0;bn<8;bn++){
      int cg = nb + wn*64 + bn*8 + 2*ql;
      float2 b2 = *(const float2*)(bo + cg);
      *(float2*)(out + (size_t)rowa*HD + cg) = make_float2(acc[am][bn][0]+b2.x, acc[am][bn][1]+b2.y);
      *(float2*)(out + (size_t)(rowa+8)*HD + cg) = make_float2(acc[am][bn][2]+b2.x, acc[am][bn][3]+b2.y);
    }
  }
}

// ---- launch ------------------------------------------------------------------
extern "C" void kernel_launch(void* const* d_in, const int* in_sizes, int n_in,
                              void* d_out, int out_size){
  const float* msa      = (const float*)d_in[0];
  const float* pair     = (const float*)d_in[1];
  const float* ln_msa_g = (const float*)d_in[2];
  const float* ln_msa_b = (const float*)d_in[3];
  const float* ln_pair_g= (const float*)d_in[4];
  const float* ln_pair_b= (const float*)d_in[5];
  const float* sw_wq    = (const float*)d_in[6];
  const float* sw_bq    = (const float*)d_in[7];
  const float* sw_wk    = (const float*)d_in[8];
  const float* sw_bk    = (const float*)d_in[9];
  const float* wq       = (const float*)d_in[10];
  const float* wk       = (const float*)d_in[11];
  const float* wv       = (const float*)d_in[12];
  const float* wb       = (const float*)d_in[13];
  const float* wg       = (const float*)d_in[14];
  const float* bg       = (const float*)d_in[15];
  const float* wo       = (const float*)d_in[16];
  const float* bo       = (const float*)d_in[17];
  float* out = (float*)d_out;

  cudaFuncSetAttribute(k_proj, cudaFuncAttributeMaxDynamicSharedMemorySize, PROJ_SMEM);
  cudaFuncSetAttribute(k_attn, cudaFuncAttributeMaxDynamicSharedMemorySize, ATTN_SMEM);
  cudaFuncSetAttribute(k_pv,   cudaFuncAttributeMaxDynamicSharedMemorySize, PV_SMEM);
  cudaFuncSetAttribute(k_out,  cudaFuncAttributeMaxDynamicSharedMemorySize, PROJ_SMEM);
  cudaFuncSetAttribute(k_pbmm, cudaFuncAttributeMaxDynamicSharedMemorySize, PB_SMEM);

  k_prep<<<6*256, 256>>>(sw_wk, wq, wk, wv, wg, wo);          // 1
  k_qsw<<<Ll, 256>>>(msa, ln_msa_g, ln_msa_b, sw_wq, sw_bq);  // 2
  k_ln<<<NL/32, 256>>>(msa, ln_msa_g, ln_msa_b);              // 3
  k_proj<<<dim3(10, NL/128), 256, PROJ_SMEM>>>(sw_bk, bg);    // 4 (ncu slot)
  k_pbmm<<<LLc/128, 256, PB_SMEM>>>(pair, ln_pair_g, ln_pair_b, wb); // 5
  k_swl<<<Ll, 256>>>();                                       // 6
  k_qs<<<NL*HD/1024, 256>>>();                                // 7
  k_attn<<<dim3(3,6,8), 256, ATTN_SMEM>>>();                  // 8
  k_attnsoftmax<<<Hh*Ll, 128>>>();                            // 9
  k_pv<<<dim3(3,64,8), 256, PV_SMEM>>>();                     // 10
  k_out<<<dim3(2, NL/128), 256, PROJ_SMEM>>>(bo, out);        // 11
}